// round 5
// baseline (speedup 1.0000x reference)
#include <cuda_runtime.h>
#include <math.h>

// Problem constants
#define B_SZ 2
#define T_SEQ 2048
#define E_DIM 2048
#define NHEAD 16
#define NOPE 64
#define ROPE 32
#define VD 64
#define KVR 256
#define QKD 96
#define DLAT 288        // KVR + ROPE
#define ROWS 4096       // B*T

// ---------------- scratch (device globals: allocation-free) ----------------
__device__ float g_kvall[ROWS * 288];
__device__ float g_kvnorm[ROWS * 256];
__device__ float g_q[ROWS * 1536];          // after rope: per head [nope(64)|roped pe(32)]
__device__ float g_klat[ROWS * DLAT];       // [0:256]=kv_t, [256:288]=roped k_pe
__device__ float g_klath[ROWS * 2048];      // per (row,h): [kabs(64)|vabs(64)]
__device__ float g_c2[T_SEQ * 64];
__device__ float g_p2[ROWS * 64];
__device__ float g_xv[ROWS * 1024];         // attention output per head (64 dims)
__device__ float g_wbT[256 * 2048];         // wkv_b transposed: [c][h*128+d]

__device__ __forceinline__ unsigned f2tf32(float f) {
    unsigned r; asm("cvt.rna.tf32.f32 %0, %1;" : "=r"(r) : "f"(f)); return r;
}

// ============================================================================
// TF32 tensor-core GEMM: C[M,N] = A[M,K] @ B[K,N]  (row-major, batched strides)
// ============================================================================
#define MMA_BM 128
#define MMA_BN 128
#define MMA_BK 32
#define AS_STRIDE 36
#define BS_STRIDE 136
#define STAGE_A (MMA_BM * AS_STRIDE)
#define STAGE_B (MMA_BK * BS_STRIDE)
#define MMA_SMEM (2 * (STAGE_A + STAGE_B) * 4)

__global__ __launch_bounds__(256) void mma_gemm_kernel(
    int M, int N, int K,
    const float* __restrict__ A, int lda, long long sA,
    const float* __restrict__ B, int ldb, long long sB,
    float* __restrict__ C, int ldc, long long sC)
{
    extern __shared__ float smf[];
    float* As = smf;
    float* Bs = smf + 2 * STAGE_A;

    A += (long long)blockIdx.z * sA;
    B += (long long)blockIdx.z * sB;
    C += (long long)blockIdx.z * sC;

    const int tid  = threadIdx.x;
    const int lane = tid & 31;
    const int wid  = tid >> 5;
    const int warp_m = (wid & 1) * 64;
    const int warp_n = (wid >> 1) * 32;
    const int bm = blockIdx.y * MMA_BM;
    const int bn = blockIdx.x * MMA_BN;

    float acc[4][4][4];
    #pragma unroll
    for (int mt = 0; mt < 4; mt++)
        #pragma unroll
        for (int nt = 0; nt < 4; nt++)
            #pragma unroll
            for (int i = 0; i < 4; i++) acc[mt][nt][i] = 0.f;

    const int nk = K / MMA_BK;

    auto load_stage = [&](int stage, int k0) {
        #pragma unroll
        for (int i = 0; i < 4; i++) {
            int c = tid + 256 * i;
            int row = c >> 3, col = (c & 7) * 4;
            unsigned dst = (unsigned)__cvta_generic_to_shared(
                &As[stage * STAGE_A + row * AS_STRIDE + col]);
            const float* src = A + (size_t)(bm + row) * lda + k0 + col;
            asm volatile("cp.async.cg.shared.global [%0], [%1], 16;"
                         :: "r"(dst), "l"(src));
        }
        #pragma unroll
        for (int i = 0; i < 4; i++) {
            int c = tid + 256 * i;
            int k = c >> 5, col = (c & 31) * 4;
            unsigned dst = (unsigned)__cvta_generic_to_shared(
                &Bs[stage * STAGE_B + k * BS_STRIDE + col]);
            int gn = bn + col;
            bool ok = (gn < N);
            const float* src = ok ? (B + (size_t)(k0 + k) * ldb + gn) : B;
            int sz = ok ? 16 : 0;
            asm volatile("cp.async.cg.shared.global [%0], [%1], 16, %2;"
                         :: "r"(dst), "l"(src), "r"(sz));
        }
    };

    load_stage(0, 0);
    asm volatile("cp.async.commit_group;");

    for (int kt = 0; kt < nk; kt++) {
        if (kt + 1 < nk) load_stage((kt + 1) & 1, (kt + 1) * MMA_BK);
        asm volatile("cp.async.commit_group;");
        asm volatile("cp.async.wait_group 1;");
        __syncthreads();

        const float* a_s = As + (kt & 1) * STAGE_A;
        const float* b_s = Bs + (kt & 1) * STAGE_B;

        #pragma unroll
        for (int kk = 0; kk < 4; kk++) {
            const int kb = kk * 8;
            unsigned af[4][4], bf[4][2];
            #pragma unroll
            for (int mt = 0; mt < 4; mt++) {
                int r0 = warp_m + mt * 16 + (lane >> 2);
                int kc = kb + (lane & 3);
                af[mt][0] = f2tf32(a_s[r0 * AS_STRIDE + kc]);
                af[mt][1] = f2tf32(a_s[(r0 + 8) * AS_STRIDE + kc]);
                af[mt][2] = f2tf32(a_s[r0 * AS_STRIDE + kc + 4]);
                af[mt][3] = f2tf32(a_s[(r0 + 8) * AS_STRIDE + kc + 4]);
            }
            #pragma unroll
            for (int nt = 0; nt < 4; nt++) {
                int col = warp_n + nt * 8 + (lane >> 2);
                bf[nt][0] = f2tf32(b_s[(kb + (lane & 3)) * BS_STRIDE + col]);
                bf[nt][1] = f2tf32(b_s[(kb + 4 + (lane & 3)) * BS_STRIDE + col]);
            }
            #pragma unroll
            for (int mt = 0; mt < 4; mt++)
                #pragma unroll
                for (int nt = 0; nt < 4; nt++)
                    asm volatile(
                        "mma.sync.aligned.m16n8k8.row.col.f32.tf32.tf32.f32 "
                        "{%0,%1,%2,%3}, {%4,%5,%6,%7}, {%8,%9}, {%0,%1,%2,%3};"
                        : "+f"(acc[mt][nt][0]), "+f"(acc[mt][nt][1]),
                          "+f"(acc[mt][nt][2]), "+f"(acc[mt][nt][3])
                        : "r"(af[mt][0]), "r"(af[mt][1]), "r"(af[mt][2]), "r"(af[mt][3]),
                          "r"(bf[nt][0]), "r"(bf[nt][1]));
        }
        __syncthreads();
    }

    #pragma unroll
    for (int mt = 0; mt < 4; mt++) {
        #pragma unroll
        for (int nt = 0; nt < 4; nt++) {
            int r0 = bm + warp_m + mt * 16 + (lane >> 2);
            int cn = bn + warp_n + nt * 8 + (lane & 3) * 2;
            if (cn < N) {
                *(float2*)&C[(size_t)r0 * ldc + cn] =
                    make_float2(acc[mt][nt][0], acc[mt][nt][1]);
                *(float2*)&C[(size_t)(r0 + 8) * ldc + cn] =
                    make_float2(acc[mt][nt][2], acc[mt][nt][3]);
            }
        }
    }
}

// ---------------- full transpose of wkv_b: wbT[c][n] = wkv_b[n][c] ----------------
__global__ void wbt_kernel(const float* __restrict__ wkv_b, float* __restrict__ wbT)
{
    int idx = blockIdx.x * 256 + threadIdx.x;   // 524288
    int n = idx & 2047, c = idx >> 11;
    wbT[(size_t)c * 2048 + n] = wkv_b[(size_t)n * 256 + c];
}

// ---------------- small FFMA SGEMM (P2 only) ----------------
template<int BM,int BN,int BK,int TM,int TN>
__global__ void sgemm_kernel(int M,int N,int K,
    const float* __restrict__ A,int lda,
    const float* __restrict__ B,int ldb,
    float* __restrict__ C,int ldc,
    const float* __restrict__ bias)
{
    constexpr int THREADS=(BM/TM)*(BN/TN);
    __shared__ float As[BK][BM+1];
    __shared__ float Bs[BK][BN+1];
    const int bm = blockIdx.y*BM, bn = blockIdx.x*BN;
    const int tid = threadIdx.x;
    const int tcol = tid % (BN/TN), trow = tid / (BN/TN);
    float acc[TM][TN];
    #pragma unroll
    for (int i=0;i<TM;i++)
        #pragma unroll
        for (int j=0;j<TN;j++) acc[i][j]=0.f;

    for (int k0=0;k0<K;k0+=BK) {
        for (int idx=tid; idx<BM*BK; idx+=THREADS) {
            int m = idx / BK, kk = idx - m*BK;
            int gm = bm+m, gk = k0+kk;
            As[kk][m] = (gm<M && gk<K) ? A[(long long)gm*lda+gk] : 0.f;
        }
        for (int idx=tid; idx<BK*BN; idx+=THREADS) {
            int kk = idx / BN, n = idx - kk*BN;
            int gk = k0+kk, gn = bn+n;
            Bs[kk][n] = (gk<K && gn<N) ? B[(long long)gk*ldb+gn] : 0.f;
        }
        __syncthreads();
        #pragma unroll
        for (int kk=0;kk<BK;kk++) {
            float ra[TM], rb[TN];
            #pragma unroll
            for (int i=0;i<TM;i++) ra[i] = As[kk][trow*TM+i];
            #pragma unroll
            for (int j=0;j<TN;j++) rb[j] = Bs[kk][tcol*TN+j];
            #pragma unroll
            for (int i=0;i<TM;i++)
                #pragma unroll
                for (int j=0;j<TN;j++) acc[i][j] += ra[i]*rb[j];
        }
        __syncthreads();
    }
    #pragma unroll
    for (int i=0;i<TM;i++) {
        int gm = bm + trow*TM + i;
        if (gm >= M) continue;
        #pragma unroll
        for (int j=0;j<TN;j++) {
            int gn = bn + tcol*TN + j;
            if (gn < N) {
                float v = acc[i][j];
                if (bias) v += bias[gn];
                C[(long long)gm*ldc+gn] = v;
            }
        }
    }
}

// ---------------- kv post: layernorm(kv) + rope(k_pe) ----------------
__global__ void kv_post_kernel(const float* __restrict__ kvall,
                               const float* __restrict__ gamma,
                               const float* __restrict__ beta,
                               const int* __restrict__ position,
                               float* __restrict__ kvnorm,
                               float* __restrict__ klat)
{
    int row = blockIdx.x;
    int tid = threadIdx.x;
    __shared__ float red[256];
    float v = kvall[(size_t)row*288 + tid];
    red[tid] = v;
    __syncthreads();
    for (int s=128;s>0;s>>=1){ if (tid<s) red[tid]+=red[tid+s]; __syncthreads(); }
    float mean = red[0] * (1.f/256.f);
    __syncthreads();
    float d = v - mean;
    red[tid] = d*d;
    __syncthreads();
    for (int s=128;s>0;s>>=1){ if (tid<s) red[tid]+=red[tid+s]; __syncthreads(); }
    float var = red[0] * (1.f/256.f);
    float rstd = rsqrtf(var + 1e-5f);
    kvnorm[(size_t)row*256 + tid] = d*rstd*gamma[tid] + beta[tid];

    if (tid < 16) {
        int t = row & (T_SEQ-1);
        float pos = (float)position[t];
        float freq = expf(-(float)(2*tid) * (9.2103403719761836f/32.f));
        float a = pos * freq;
        float c = cosf(a), s = sinf(a);
        float x0 = kvall[(size_t)row*288 + 256 + 2*tid];
        float x1 = kvall[(size_t)row*288 + 257 + 2*tid];
        klat[(size_t)row*288 + 256 + 2*tid] = x0*c - x1*s;
        klat[(size_t)row*288 + 257 + 2*tid] = x0*s + x1*c;
    }
}

// ---------------- rope for q_pe, IN PLACE in g_q ----------------
__global__ void q_rope_kernel(float* __restrict__ q,
                              const int* __restrict__ position)
{
    int row = blockIdx.x;
    int tid = threadIdx.x;          // 256 = 16 heads * 16 pairs
    int h = tid >> 4, i = tid & 15;
    int t = row & (T_SEQ-1);
    float pos = (float)position[t];
    float freq = expf(-(float)(2*i) * (9.2103403719761836f/32.f));
    float a = pos * freq;
    float c = cosf(a), s = sinf(a);
    float* qr = q + (size_t)row*1536 + h*96 + 64;
    float x0 = qr[2*i], x1 = qr[2*i+1];
    qr[2*i]   = x0*c - x1*s;
    qr[2*i+1] = x0*s + x1*c;
}

// ---------------- C2 ----------------
__global__ void c2_kernel(const float* __restrict__ w,
                          const float* __restrict__ bias,
                          float* __restrict__ c2)
{
    __shared__ float pe[256];
    int p = blockIdx.x;
    int tid = threadIdx.x;
    int i = tid >> 1;
    float freq = expf(-(float)(2*i) * (9.2103403719761836f/256.f));
    float a = (float)p * freq;
    pe[tid] = (tid & 1) ? cosf(a) : sinf(a);
    __syncthreads();
    if (tid < 64) {
        float acc = bias[tid];
        for (int k=0;k<256;k++) acc += pe[k]*w[k*64+tid];
        c2[(size_t)(2*p)*64 + tid]   = acc;
        c2[(size_t)(2*p+1)*64 + tid] = acc;
    }
}

// ---------------- kv_t gated combine -> klat[...,0:256] ----------------
__global__ void kvt_kernel(const float* __restrict__ c2,
                           const float* __restrict__ p2,
                           const float* __restrict__ kvnorm,
                           float* __restrict__ klat)
{
    int row = blockIdx.x;
    int tid = threadIdx.x;
    int t = row & (T_SEQ-1);
    __shared__ float r1[64], r2[64];
    if (tid < 64) {
        float a = c2[(size_t)t*64 + tid];
        r1[tid] = a * p2[(size_t)row*64 + tid];
        r2[tid] = (t & 1) ? a * p2[(size_t)(row-1)*64 + tid] : 0.f;
    }
    __syncthreads();
    for (int s=32;s>0;s>>=1){ if (tid<s){ r1[tid]+=r1[tid+s]; r2[tid]+=r2[tid+s]; } __syncthreads(); }
    float wself = 1.f/(1.f+expf(-r1[0]));
    float wprev = (t & 1) ? 1.f/(1.f+expf(-r2[0])) : 0.f;
    for (int c=tid; c<256; c+=128) {
        float v = wself * kvnorm[(size_t)row*256 + c];
        if (t & 1) v += wprev * kvnorm[(size_t)(row-1)*256 + c];
        klat[(size_t)row*288 + c] = v;
    }
}

// ============================================================================
// Tensor-core flash attention, per-head absorbed projections (tf32 mma)
// Q: 96-dim (nope|rope). K packed row: [kabs(64)|kpe(32)|vabs(64)] = 160.
// Block: 256 threads, BQ=64 queries of one (b,h). 8 warps = 4 bands x 2 halves.
// ============================================================================
#define BQ 64
#define QS2 100     // Q smem stride (96 + 4 pad)
#define KS2 164     // K/V packed smem stride (160 + 4 pad)
#define SS 36       // S smem stride
#define FLASH_SMEM ((BQ*QS2 + 2*32*KS2 + BQ*SS + 3*BQ) * 4)

__global__ __launch_bounds__(256, 2) void flash_mma_kernel(
    const float* __restrict__ q,
    const float* __restrict__ klat,
    const float* __restrict__ klath,
    float* __restrict__ x)
{
    extern __shared__ float sm[];
    float* Qs   = sm;                       // 64 x 100
    float* Ks   = sm + BQ*QS2;              // 2 x 32 x 164
    float* Ssm  = Ks + 2*32*KS2;            // 64 x 36
    float* Mrow = Ssm + BQ*SS;              // 64
    float* Lrow = Mrow + BQ;                // 64
    float* Crow = Lrow + BQ;                // 64

    const int i0 = blockIdx.x * BQ;
    const int h  = blockIdx.y;
    const int b  = blockIdx.z;
    const int tid  = threadIdx.x;
    const int lane = tid & 31;
    const int wid  = tid >> 5;
    const int band = wid >> 1;       // query rows band*16..+16
    const int half = wid & 1;        // S cols half*16; V cols half*32
    const int gid  = lane >> 2;
    const int tig  = lane & 3;
    const float scale = 0.10206207261596575f;  // 1/sqrt(96)

    // ---- Q tile cp.async: 64 rows x 96 floats ----
    const float* qbase = q + (size_t)(b*T_SEQ + i0)*1536 + h*96;
    #pragma unroll
    for (int i = 0; i < 6; i++) {
        int c = tid + 256*i;               // 0..1535
        int r = c / 24, c4 = c % 24;
        unsigned dst = (unsigned)__cvta_generic_to_shared(&Qs[r*QS2 + c4*4]);
        const float* src = qbase + (size_t)r*1536 + c4*4;
        asm volatile("cp.async.cg.shared.global [%0], [%1], 16;" :: "r"(dst), "l"(src));
    }
    asm volatile("cp.async.commit_group;");

    auto load_k = [&](int stage, int kt0) {
        #pragma unroll
        for (int i = 0; i < 5; i++) {
            int c = tid + 256*i;           // 0..1279
            int r = c / 40, cc = c % 40;
            int j = 2*(kt0 + r) + 1;
            if (j > T_SEQ-1) j = T_SEQ-1;  // clamp (masked later)
            unsigned dst = (unsigned)__cvta_generic_to_shared(
                &Ks[stage*32*KS2 + r*KS2 + cc*4]);
            const float* src;
            if (cc < 16)       src = klath + (size_t)(b*T_SEQ + j)*2048 + h*128 + cc*4;
            else if (cc < 24)  src = klat  + (size_t)(b*T_SEQ + j)*288 + 256 + (cc-16)*4;
            else               src = klath + (size_t)(b*T_SEQ + j)*2048 + h*128 + 64 + (cc-24)*4;
            asm volatile("cp.async.cg.shared.global [%0], [%1], 16;" :: "r"(dst), "l"(src));
        }
    };
    load_k(0, 0);
    asm volatile("cp.async.commit_group;");

    // wait for Q (leave K0 in flight)
    asm volatile("cp.async.wait_group 1;");
    __syncthreads();

    // ---- self score (96-dim) + softmax state init ----
    {
        int row = tid >> 2, cg = tid & 3;
        size_t gr = (size_t)(b*T_SEQ + i0 + row);
        const float* ka = klath + gr*2048 + h*128;
        const float* kp = klat  + gr*288 + 256;
        float part = 0.f;
        #pragma unroll
        for (int k = 0; k < 16; k++) {
            int c = 4*k + cg;
            part += Qs[row*QS2 + c] * ka[c];
        }
        #pragma unroll
        for (int k = 0; k < 8; k++) {
            int c = 4*k + cg;
            part += Qs[row*QS2 + 64 + c] * kp[c];
        }
        part += __shfl_xor_sync(0xffffffffu, part, 1, 4);
        part += __shfl_xor_sync(0xffffffffu, part, 2, 4);
        if (cg == 0) { Mrow[row] = part * scale; Lrow[row] = 1.f; }
    }

    // ---- O accumulator init = v_abs[self] ----
    float o[4][4];
    {
        size_t r1 = (size_t)(b*T_SEQ + i0 + band*16 + gid);
        const float* v1 = klath + r1*2048 + h*128 + 64;
        const float* v2 = klath + (r1 + 8)*2048 + h*128 + 64;
        #pragma unroll
        for (int nt = 0; nt < 4; nt++) {
            int col = half*32 + nt*8 + tig*2;
            float2 a = *(const float2*)&v1[col];
            float2 c = *(const float2*)&v2[col];
            o[nt][0] = a.x; o[nt][1] = a.y; o[nt][2] = c.x; o[nt][3] = c.y;
        }
    }
    __syncthreads();

    // ---- key-tile loop ----
    int stage = 0;
    for (int kt0 = 0; 2*kt0 + 1 < i0 + BQ; kt0 += 32) {
        bool more = (2*(kt0+32) + 1 < i0 + BQ);
        if (more) load_k(stage ^ 1, kt0 + 32);
        asm volatile("cp.async.commit_group;");
        asm volatile("cp.async.wait_group 1;");
        __syncthreads();

        const float* ks = Ks + stage*32*KS2;

        // QK^T over 96 dims: warp computes 16x16 of S
        float sf[2][4];
        #pragma unroll
        for (int nt = 0; nt < 2; nt++)
            #pragma unroll
            for (int i = 0; i < 4; i++) sf[nt][i] = 0.f;
        {
            const float* qb = Qs + (band*16)*QS2;
            const float* kb = ks + (half*16)*KS2;
            #pragma unroll
            for (int kst = 0; kst < 12; kst++) {
                int kc = kst*8 + tig;
                unsigned a0 = f2tf32(qb[gid*QS2 + kc]);
                unsigned a1 = f2tf32(qb[(gid+8)*QS2 + kc]);
                unsigned a2 = f2tf32(qb[gid*QS2 + kc + 4]);
                unsigned a3 = f2tf32(qb[(gid+8)*QS2 + kc + 4]);
                #pragma unroll
                for (int nt = 0; nt < 2; nt++) {
                    unsigned b0 = f2tf32(kb[(nt*8+gid)*KS2 + kc]);
                    unsigned b1 = f2tf32(kb[(nt*8+gid)*KS2 + kc + 4]);
                    asm volatile(
                        "mma.sync.aligned.m16n8k8.row.col.f32.tf32.tf32.f32 "
                        "{%0,%1,%2,%3}, {%4,%5,%6,%7}, {%8,%9}, {%0,%1,%2,%3};"
                        : "+f"(sf[nt][0]), "+f"(sf[nt][1]), "+f"(sf[nt][2]), "+f"(sf[nt][3])
                        : "r"(a0), "r"(a1), "r"(a2), "r"(a3), "r"(b0), "r"(b1));
                }
            }
        }
        #pragma unroll
        for (int nt = 0; nt < 2; nt++) {
            int r = band*16 + gid;
            int c = half*16 + nt*8 + tig*2;
            *(float2*)&Ssm[r*SS + c]     = make_float2(sf[nt][0], sf[nt][1]);
            *(float2*)&Ssm[(r+8)*SS + c] = make_float2(sf[nt][2], sf[nt][3]);
        }
        __syncthreads();

        // online softmax: 4 threads per row, 8 cols each
        {
            int row = tid >> 2, cg = tid & 3;
            int iq = i0 + row;
            float vals[8];
            float mx = -1e30f;
            #pragma unroll
            for (int jj = 0; jj < 8; jj++) {
                int col = cg*8 + jj;
                int j = 2*(kt0 + col) + 1;
                float s = (j < iq) ? Ssm[row*SS + col]*scale : -1e30f;
                vals[jj] = s;
                mx = fmaxf(mx, s);
            }
            mx = fmaxf(mx, __shfl_xor_sync(0xffffffffu, mx, 1, 4));
            mx = fmaxf(mx, __shfl_xor_sync(0xffffffffu, mx, 2, 4));
            float mprev = Mrow[row];
            float mnew = fmaxf(mprev, mx);
            float corr = __expf(mprev - mnew);
            float sum = 0.f;
            #pragma unroll
            for (int jj = 0; jj < 8; jj++) {
                float e = __expf(vals[jj] - mnew);
                Ssm[row*SS + cg*8 + jj] = e;
                sum += e;
            }
            sum += __shfl_xor_sync(0xffffffffu, sum, 1, 4);
            sum += __shfl_xor_sync(0xffffffffu, sum, 2, 4);
            if (cg == 0) {
                Mrow[row] = mnew;
                Lrow[row] = Lrow[row]*corr + sum;
                Crow[row] = corr;
            }
        }
        __syncthreads();

        // scale O, then P @ V (V = packed cols 96..160)
        {
            float c1 = Crow[band*16 + gid];
            float c2v = Crow[band*16 + gid + 8];
            #pragma unroll
            for (int nt = 0; nt < 4; nt++) {
                o[nt][0] *= c1; o[nt][1] *= c1;
                o[nt][2] *= c2v; o[nt][3] *= c2v;
            }
            const float* pb = Ssm + (band*16)*SS;
            #pragma unroll
            for (int kst = 0; kst < 4; kst++) {
                int kc = kst*8 + tig;
                unsigned a0 = f2tf32(pb[gid*SS + kc]);
                unsigned a1 = f2tf32(pb[(gid+8)*SS + kc]);
                unsigned a2 = f2tf32(pb[gid*SS + kc + 4]);
                unsigned a3 = f2tf32(pb[(gid+8)*SS + kc + 4]);
                #pragma unroll
                for (int nt = 0; nt < 4; nt++) {
                    int vc = 96 + half*32 + nt*8 + gid;
                    unsigned b0 = f2tf32(ks[(kst*8 + tig)*KS2 + vc]);
                    unsigned b1 = f2tf32(ks[(kst*8 + tig + 4)*KS2 + vc]);
                    asm volatile(
                        "mma.sync.aligned.m16n8k8.row.col.f32.tf32.tf32.f32 "
                        "{%0,%1,%2,%3}, {%4,%5,%6,%7}, {%8,%9}, {%0,%1,%2,%3};"
                        : "+f"(o[nt][0]), "+f"(o[nt][1]), "+f"(o[nt][2]), "+f"(o[nt][3])
                        : "r"(a0), "r"(a1), "r"(a2), "r"(a3), "r"(b0), "r"(b1));
                }
            }
        }
        __syncthreads();
        stage ^= 1;
    }

    // ---- epilogue: normalize and store x[row][h*64 + col] ----
    {
        size_t r1 = (size_t)(b*T_SEQ + i0 + band*16 + gid);
        float li1 = 1.f / Lrow[band*16 + gid];
        float li2 = 1.f / Lrow[band*16 + gid + 8];
        float* x1 = x + r1*1024 + h*64;
        float* x2 = x + (r1 + 8)*1024 + h*64;
        #pragma unroll
        for (int nt = 0; nt < 4; nt++) {
            int col = half*32 + nt*8 + tig*2;
            *(float2*)&x1[col] = make_float2(o[nt][0]*li1, o[nt][1]*li1);
            *(float2*)&x2[col] = make_float2(o[nt][2]*li2, o[nt][3]*li2);
        }
    }
}

// ---------------- host ----------------
extern "C" void kernel_launch(void* const* d_in, const int* in_sizes, int n_in,
                              void* d_out, int out_size)
{
    (void)in_sizes; (void)n_in; (void)out_size;
    const float* query    = (const float*)d_in[0];
    const float* key      = (const float*)d_in[1];
    const int*   position = (const int*)d_in[3];
    const float* wq       = (const float*)d_in[4];
    const float* wkv_a    = (const float*)d_in[5];
    const float* kv_gamma = (const float*)d_in[6];
    const float* kv_beta  = (const float*)d_in[7];
    const float* wkv_b    = (const float*)d_in[8];
    const float* wo       = (const float*)d_in[9];
    const float* fc_c_w   = (const float*)d_in[10];
    const float* fc_c_b   = (const float*)d_in[11];
    const float* fc_p_w   = (const float*)d_in[12];
    const float* fc_p_b   = (const float*)d_in[13];
    float* out = (float*)d_out;

    float *kvall, *kvnorm, *q, *klat, *klath, *c2, *p2, *xv, *wbT;
    cudaGetSymbolAddress((void**)&kvall,  g_kvall);
    cudaGetSymbolAddress((void**)&kvnorm, g_kvnorm);
    cudaGetSymbolAddress((void**)&q,      g_q);
    cudaGetSymbolAddress((void**)&klat,   g_klat);
    cudaGetSymbolAddress((void**)&klath,  g_klath);
    cudaGetSymbolAddress((void**)&c2,     g_c2);
    cudaGetSymbolAddress((void**)&p2,     g_p2);
    cudaGetSymbolAddress((void**)&xv,     g_xv);
    cudaGetSymbolAddress((void**)&wbT,    g_wbT);

    cudaFuncSetAttribute(flash_mma_kernel, cudaFuncAttributeMaxDynamicSharedMemorySize, FLASH_SMEM);
    cudaFuncSetAttribute(mma_gemm_kernel, cudaFuncAttributeMaxDynamicSharedMemorySize, MMA_SMEM);

    // 0. full transpose of wkv_b -> wbT [256 x 2048]
    wbt_kernel<<<2048,256>>>(wkv_b, wbT);

    // 1. kv_all = key @ wkv_a           (4096 x 288 x 2048)
    mma_gemm_kernel<<<dim3(3,32,1),256,MMA_SMEM>>>(
        ROWS,288,E_DIM, key,E_DIM,0, wkv_a,288,0, kvall,288,0);

    // 2. layernorm + k_pe rope
    kv_post_kernel<<<ROWS,256>>>(kvall, kv_gamma, kv_beta, position, kvnorm, klat);

    // 3. q = query @ wq                 (4096 x 1536 x 2048)
    mma_gemm_kernel<<<dim3(12,32,1),256,MMA_SMEM>>>(
        ROWS,1536,E_DIM, query,E_DIM,0, wq,1536,0, q,1536,0);

    // 4. q_pe rope (in place)
    q_rope_kernel<<<ROWS,256>>>(q, position);

    // 5. C2
    c2_kernel<<<1024,256>>>(fc_c_w, fc_c_b, c2);

    // 6. P2 = kv_norm @ fc_p_w + b
    sgemm_kernel<64,64,16,4,4><<<dim3(1,64,1),256>>>(
        ROWS,64,256, kvnorm,256, fc_p_w,64, p2,64, fc_p_b);

    // 7. kv_t gated combine -> klat[0:256]
    kvt_kernel<<<ROWS,128>>>(c2, p2, kvnorm, klat);

    // 8. klath = kv_t @ wbT             (4096 x 2048 x 256): per-head [kabs|vabs]
    mma_gemm_kernel<<<dim3(16,32,1),256,MMA_SMEM>>>(
        ROWS,2048,KVR, klat,DLAT,0, wbT,2048,0, klath,2048,0);

    // 9. flash attention (96-dim QK, 64-dim PV per head)
    flash_mma_kernel<<<dim3(T_SEQ/BQ,NHEAD,B_SZ),256,FLASH_SMEM>>>(q, klat, klath, xv);

    // 10. out = xv @ wo                 (4096 x 2048 x 1024)
    mma_gemm_kernel<<<dim3(16,32,1),256,MMA_SMEM>>>(
        ROWS,E_DIM,1024, xv,1024,0, wo,E_DIM,0, out,E_DIM,0);
}

// round 8
// speedup vs baseline: 1.4576x; 1.4576x over previous
#include <cuda_runtime.h>
#include <math.h>

// Problem constants
#define B_SZ 2
#define T_SEQ 2048
#define E_DIM 2048
#define NHEAD 16
#define NOPE 64
#define ROPE 32
#define VD 64
#define KVR 256
#define QKD 96
#define DLAT 288        // KVR + ROPE
#define ROWS 4096       // B*T

// ---------------- scratch (device globals: allocation-free) ----------------
__device__ float g_kvall[ROWS * 288];
__device__ float g_kvnorm[ROWS * 256];
__device__ float g_q[ROWS * 1536];          // tf32-rounded; per head [nope|roped pe]
__device__ float g_klat[ROWS * DLAT];       // tf32-rounded; [0:256]=kv_t, [256:288]=k_pe
__device__ float g_klath[ROWS * 2048];      // tf32-rounded; per (row,h): [kabs|vabs]
__device__ float g_c2[T_SEQ * 64];
__device__ float g_p2[ROWS * 64];
__device__ float g_xv[ROWS * 1024];         // tf32-rounded attention output
__device__ float g_wbT[256 * 2048];         // tf32-rounded transpose of wkv_b
// tf32-rounded copies of raw inputs
__device__ float g_queryr[ROWS * E_DIM];
__device__ float g_keyr[ROWS * E_DIM];
__device__ float g_wqr[E_DIM * 1536];
__device__ float g_wkvar[E_DIM * 288];
__device__ float g_wor[1024 * E_DIM];

__device__ __forceinline__ unsigned f2tf32(float f) {
    unsigned r; asm("cvt.rna.tf32.f32 %0, %1;" : "=r"(r) : "f"(f)); return r;
}
__device__ __forceinline__ float rnd32(float f) {
    return __uint_as_float(f2tf32(f));
}

// ---------------- vectorized tf32-round copy ----------------
__global__ void round_kernel(const float4* __restrict__ src, float4* __restrict__ dst, int n4)
{
    int i = blockIdx.x * 256 + threadIdx.x;
    if (i < n4) {
        float4 v = src[i];
        v.x = rnd32(v.x); v.y = rnd32(v.y); v.z = rnd32(v.z); v.w = rnd32(v.w);
        dst[i] = v;
    }
}

// ============================================================================
// TF32 tensor-core GEMM (inputs pre-rounded to tf32; no cvt in mainloop)
// ============================================================================
#define MMA_BM 128
#define MMA_BN 128
#define MMA_BK 32
#define AS_STRIDE 36
#define BS_STRIDE 136
#define STAGE_A (MMA_BM * AS_STRIDE)
#define STAGE_B (MMA_BK * BS_STRIDE)
#define MMA_SMEM (2 * (STAGE_A + STAGE_B) * 4)

__global__ __launch_bounds__(256) void mma_gemm_kernel(
    int M, int N, int K,
    const float* __restrict__ A, int lda, long long sA,
    const float* __restrict__ B, int ldb, long long sB,
    float* __restrict__ C, int ldc, long long sC,
    int round_out)
{
    extern __shared__ float smf[];
    float* As = smf;
    float* Bs = smf + 2 * STAGE_A;

    A += (long long)blockIdx.z * sA;
    B += (long long)blockIdx.z * sB;
    C += (long long)blockIdx.z * sC;

    const int tid  = threadIdx.x;
    const int lane = tid & 31;
    const int wid  = tid >> 5;
    const int warp_m = (wid & 1) * 64;
    const int warp_n = (wid >> 1) * 32;
    const int bm = blockIdx.y * MMA_BM;
    const int bn = blockIdx.x * MMA_BN;

    float acc[4][4][4];
    #pragma unroll
    for (int mt = 0; mt < 4; mt++)
        #pragma unroll
        for (int nt = 0; nt < 4; nt++)
            #pragma unroll
            for (int i = 0; i < 4; i++) acc[mt][nt][i] = 0.f;

    const int nk = K / MMA_BK;

    auto load_stage = [&](int stage, int k0) {
        #pragma unroll
        for (int i = 0; i < 4; i++) {
            int c = tid + 256 * i;
            int row = c >> 3, col = (c & 7) * 4;
            unsigned dst = (unsigned)__cvta_generic_to_shared(
                &As[stage * STAGE_A + row * AS_STRIDE + col]);
            const float* src = A + (size_t)(bm + row) * lda + k0 + col;
            asm volatile("cp.async.cg.shared.global [%0], [%1], 16;"
                         :: "r"(dst), "l"(src));
        }
        #pragma unroll
        for (int i = 0; i < 4; i++) {
            int c = tid + 256 * i;
            int k = c >> 5, col = (c & 31) * 4;
            unsigned dst = (unsigned)__cvta_generic_to_shared(
                &Bs[stage * STAGE_B + k * BS_STRIDE + col]);
            int gn = bn + col;
            bool ok = (gn < N);
            const float* src = ok ? (B + (size_t)(k0 + k) * ldb + gn) : B;
            int sz = ok ? 16 : 0;
            asm volatile("cp.async.cg.shared.global [%0], [%1], 16, %2;"
                         :: "r"(dst), "l"(src), "r"(sz));
        }
    };

    load_stage(0, 0);
    asm volatile("cp.async.commit_group;");

    for (int kt = 0; kt < nk; kt++) {
        if (kt + 1 < nk) load_stage((kt + 1) & 1, (kt + 1) * MMA_BK);
        asm volatile("cp.async.commit_group;");
        asm volatile("cp.async.wait_group 1;");
        __syncthreads();

        const float* a_s = As + (kt & 1) * STAGE_A;
        const float* b_s = Bs + (kt & 1) * STAGE_B;

        #pragma unroll
        for (int kk = 0; kk < 4; kk++) {
            const int kb = kk * 8;
            unsigned af[4][4], bf[4][2];
            #pragma unroll
            for (int mt = 0; mt < 4; mt++) {
                int r0 = warp_m + mt * 16 + (lane >> 2);
                int kc = kb + (lane & 3);
                af[mt][0] = __float_as_uint(a_s[r0 * AS_STRIDE + kc]);
                af[mt][1] = __float_as_uint(a_s[(r0 + 8) * AS_STRIDE + kc]);
                af[mt][2] = __float_as_uint(a_s[r0 * AS_STRIDE + kc + 4]);
                af[mt][3] = __float_as_uint(a_s[(r0 + 8) * AS_STRIDE + kc + 4]);
            }
            #pragma unroll
            for (int nt = 0; nt < 4; nt++) {
                int col = warp_n + nt * 8 + (lane >> 2);
                bf[nt][0] = __float_as_uint(b_s[(kb + (lane & 3)) * BS_STRIDE + col]);
                bf[nt][1] = __float_as_uint(b_s[(kb + 4 + (lane & 3)) * BS_STRIDE + col]);
            }
            #pragma unroll
            for (int mt = 0; mt < 4; mt++)
                #pragma unroll
                for (int nt = 0; nt < 4; nt++)
                    asm volatile(
                        "mma.sync.aligned.m16n8k8.row.col.f32.tf32.tf32.f32 "
                        "{%0,%1,%2,%3}, {%4,%5,%6,%7}, {%8,%9}, {%0,%1,%2,%3};"
                        : "+f"(acc[mt][nt][0]), "+f"(acc[mt][nt][1]),
                          "+f"(acc[mt][nt][2]), "+f"(acc[mt][nt][3])
                        : "r"(af[mt][0]), "r"(af[mt][1]), "r"(af[mt][2]), "r"(af[mt][3]),
                          "r"(bf[nt][0]), "r"(bf[nt][1]));
        }
        __syncthreads();
    }

    #pragma unroll
    for (int mt = 0; mt < 4; mt++) {
        #pragma unroll
        for (int nt = 0; nt < 4; nt++) {
            int r0 = bm + warp_m + mt * 16 + (lane >> 2);
            int cn = bn + warp_n + nt * 8 + (lane & 3) * 2;
            if (cn < N) {
                float v0 = acc[mt][nt][0], v1 = acc[mt][nt][1];
                float v2 = acc[mt][nt][2], v3 = acc[mt][nt][3];
                if (round_out) {
                    v0 = rnd32(v0); v1 = rnd32(v1); v2 = rnd32(v2); v3 = rnd32(v3);
                }
                *(float2*)&C[(size_t)r0 * ldc + cn]       = make_float2(v0, v1);
                *(float2*)&C[(size_t)(r0 + 8) * ldc + cn] = make_float2(v2, v3);
            }
        }
    }
}

// ---------------- transpose + round wkv_b: wbT[c][n] = wkv_b[n][c] ----------------
__global__ void wbt_kernel(const float* __restrict__ wkv_b, float* __restrict__ wbT)
{
    int idx = blockIdx.x * 256 + threadIdx.x;
    int n = idx & 2047, c = idx >> 11;
    wbT[(size_t)c * 2048 + n] = rnd32(wkv_b[(size_t)n * 256 + c]);
}

// ---------------- small FFMA SGEMM (P2 only) ----------------
template<int BM,int BN,int BK,int TM,int TN>
__global__ void sgemm_kernel(int M,int N,int K,
    const float* __restrict__ A,int lda,
    const float* __restrict__ B,int ldb,
    float* __restrict__ C,int ldc,
    const float* __restrict__ bias)
{
    constexpr int THREADS=(BM/TM)*(BN/TN);
    __shared__ float As[BK][BM+1];
    __shared__ float Bs[BK][BN+1];
    const int bm = blockIdx.y*BM, bn = blockIdx.x*BN;
    const int tid = threadIdx.x;
    const int tcol = tid % (BN/TN), trow = tid / (BN/TN);
    float acc[TM][TN];
    #pragma unroll
    for (int i=0;i<TM;i++)
        #pragma unroll
        for (int j=0;j<TN;j++) acc[i][j]=0.f;

    for (int k0=0;k0<K;k0+=BK) {
        for (int idx=tid; idx<BM*BK; idx+=THREADS) {
            int m = idx / BK, kk = idx - m*BK;
            int gm = bm+m, gk = k0+kk;
            As[kk][m] = (gm<M && gk<K) ? A[(long long)gm*lda+gk] : 0.f;
        }
        for (int idx=tid; idx<BK*BN; idx+=THREADS) {
            int kk = idx / BN, n = idx - kk*BN;
            int gk = k0+kk, gn = bn+n;
            Bs[kk][n] = (gk<K && gn<N) ? B[(long long)gk*ldb+gn] : 0.f;
        }
        __syncthreads();
        #pragma unroll
        for (int kk=0;kk<BK;kk++) {
            float ra[TM], rb[TN];
            #pragma unroll
            for (int i=0;i<TM;i++) ra[i] = As[kk][trow*TM+i];
            #pragma unroll
            for (int j=0;j<TN;j++) rb[j] = Bs[kk][tcol*TN+j];
            #pragma unroll
            for (int i=0;i<TM;i++)
                #pragma unroll
                for (int j=0;j<TN;j++) acc[i][j] += ra[i]*rb[j];
        }
        __syncthreads();
    }
    #pragma unroll
    for (int i=0;i<TM;i++) {
        int gm = bm + trow*TM + i;
        if (gm >= M) continue;
        #pragma unroll
        for (int j=0;j<TN;j++) {
            int gn = bn + tcol*TN + j;
            if (gn < N) {
                float v = acc[i][j];
                if (bias) v += bias[gn];
                C[(long long)gm*ldc+gn] = v;
            }
        }
    }
}

// ---------------- kv post: layernorm(kv) + rope(k_pe) ----------------
__global__ void kv_post_kernel(const float* __restrict__ kvall,
                               const float* __restrict__ gamma,
                               const float* __restrict__ beta,
                               const int* __restrict__ position,
                               float* __restrict__ kvnorm,
                               float* __restrict__ klat)
{
    int row = blockIdx.x;
    int tid = threadIdx.x;
    __shared__ float red[256];
    float v = kvall[(size_t)row*288 + tid];
    red[tid] = v;
    __syncthreads();
    for (int s=128;s>0;s>>=1){ if (tid<s) red[tid]+=red[tid+s]; __syncthreads(); }
    float mean = red[0] * (1.f/256.f);
    __syncthreads();
    float d = v - mean;
    red[tid] = d*d;
    __syncthreads();
    for (int s=128;s>0;s>>=1){ if (tid<s) red[tid]+=red[tid+s]; __syncthreads(); }
    float var = red[0] * (1.f/256.f);
    float rstd = rsqrtf(var + 1e-5f);
    kvnorm[(size_t)row*256 + tid] = d*rstd*gamma[tid] + beta[tid];

    if (tid < 16) {
        int t = row & (T_SEQ-1);
        float pos = (float)position[t];
        float freq = expf(-(float)(2*tid) * (9.2103403719761836f/32.f));
        float a = pos * freq;
        float c = cosf(a), s = sinf(a);
        float x0 = kvall[(size_t)row*288 + 256 + 2*tid];
        float x1 = kvall[(size_t)row*288 + 257 + 2*tid];
        klat[(size_t)row*288 + 256 + 2*tid] = rnd32(x0*c - x1*s);
        klat[(size_t)row*288 + 257 + 2*tid] = rnd32(x0*s + x1*c);
    }
}

// ---------------- rope for q_pe, IN PLACE (rounded) ----------------
__global__ void q_rope_kernel(float* __restrict__ q,
                              const int* __restrict__ position)
{
    int row = blockIdx.x;
    int tid = threadIdx.x;          // 256 = 16 heads * 16 pairs
    int h = tid >> 4, i = tid & 15;
    int t = row & (T_SEQ-1);
    float pos = (float)position[t];
    float freq = expf(-(float)(2*i) * (9.2103403719761836f/32.f));
    float a = pos * freq;
    float c = cosf(a), s = sinf(a);
    float* qr = q + (size_t)row*1536 + h*96 + 64;
    float x0 = qr[2*i], x1 = qr[2*i+1];
    qr[2*i]   = rnd32(x0*c - x1*s);
    qr[2*i+1] = rnd32(x0*s + x1*c);
}

// ---------------- C2 ----------------
__global__ void c2_kernel(const float* __restrict__ w,
                          const float* __restrict__ bias,
                          float* __restrict__ c2)
{
    __shared__ float pe[256];
    int p = blockIdx.x;
    int tid = threadIdx.x;
    int i = tid >> 1;
    float freq = expf(-(float)(2*i) * (9.2103403719761836f/256.f));
    float a = (float)p * freq;
    pe[tid] = (tid & 1) ? cosf(a) : sinf(a);
    __syncthreads();
    if (tid < 64) {
        float acc = bias[tid];
        for (int k=0;k<256;k++) acc += pe[k]*w[k*64+tid];
        c2[(size_t)(2*p)*64 + tid]   = acc;
        c2[(size_t)(2*p+1)*64 + tid] = acc;
    }
}

// ---------------- kv_t gated combine -> klat[...,0:256] (rounded) ----------------
__global__ void kvt_kernel(const float* __restrict__ c2,
                           const float* __restrict__ p2,
                           const float* __restrict__ kvnorm,
                           float* __restrict__ klat)
{
    int row = blockIdx.x;
    int tid = threadIdx.x;
    int t = row & (T_SEQ-1);
    __shared__ float r1[64], r2[64];
    if (tid < 64) {
        float a = c2[(size_t)t*64 + tid];
        r1[tid] = a * p2[(size_t)row*64 + tid];
        r2[tid] = (t & 1) ? a * p2[(size_t)(row-1)*64 + tid] : 0.f;
    }
    __syncthreads();
    for (int s=32;s>0;s>>=1){ if (tid<s){ r1[tid]+=r1[tid+s]; r2[tid]+=r2[tid+s]; } __syncthreads(); }
    float wself = 1.f/(1.f+expf(-r1[0]));
    float wprev = (t & 1) ? 1.f/(1.f+expf(-r2[0])) : 0.f;
    for (int c=tid; c<256; c+=128) {
        float v = wself * kvnorm[(size_t)row*256 + c];
        if (t & 1) v += wprev * kvnorm[(size_t)(row-1)*256 + c];
        klat[(size_t)row*288 + c] = rnd32(v);
    }
}

// ============================================================================
// Tensor-core flash attention (all operands pre-rounded tf32; raw-bit feed)
// Q: 96-dim. K packed: [kabs(64)|kpe(32)|vabs(64)] = 160.
// ============================================================================
#define BQ 64
#define QS2 100
#define KS2 164
#define SS 36
#define FLASH_SMEM ((BQ*QS2 + 2*32*KS2 + BQ*SS + 3*BQ) * 4)

__global__ __launch_bounds__(256, 2) void flash_mma_kernel(
    const float* __restrict__ q,
    const float* __restrict__ klat,
    const float* __restrict__ klath,
    float* __restrict__ x)
{
    extern __shared__ float sm[];
    float* Qs   = sm;                       // 64 x 100
    float* Ks   = sm + BQ*QS2;              // 2 x 32 x 164
    float* Ssm  = Ks + 2*32*KS2;            // 64 x 36
    float* Mrow = Ssm + BQ*SS;              // 64
    float* Lrow = Mrow + BQ;                // 64
    float* Crow = Lrow + BQ;                // 64

    const int i0 = blockIdx.x * BQ;
    const int h  = blockIdx.y;
    const int b  = blockIdx.z;
    const int tid  = threadIdx.x;
    const int lane = tid & 31;
    const int wid  = tid >> 5;
    const int band = wid >> 1;
    const int half = wid & 1;
    const int gid  = lane >> 2;
    const int tig  = lane & 3;
    const float scale = 0.10206207261596575f;  // 1/sqrt(96)

    const float* qbase = q + (size_t)(b*T_SEQ + i0)*1536 + h*96;
    #pragma unroll
    for (int i = 0; i < 6; i++) {
        int c = tid + 256*i;
        int r = c / 24, c4 = c % 24;
        unsigned dst = (unsigned)__cvta_generic_to_shared(&Qs[r*QS2 + c4*4]);
        const float* src = qbase + (size_t)r*1536 + c4*4;
        asm volatile("cp.async.cg.shared.global [%0], [%1], 16;" :: "r"(dst), "l"(src));
    }
    asm volatile("cp.async.commit_group;");

    auto load_k = [&](int stage, int kt0) {
        #pragma unroll
        for (int i = 0; i < 5; i++) {
            int c = tid + 256*i;
            int r = c / 40, cc = c % 40;
            int j = 2*(kt0 + r) + 1;
            if (j > T_SEQ-1) j = T_SEQ-1;
            unsigned dst = (unsigned)__cvta_generic_to_shared(
                &Ks[stage*32*KS2 + r*KS2 + cc*4]);
            const float* src;
            if (cc < 16)       src = klath + (size_t)(b*T_SEQ + j)*2048 + h*128 + cc*4;
            else if (cc < 24)  src = klat  + (size_t)(b*T_SEQ + j)*288 + 256 + (cc-16)*4;
            else               src = klath + (size_t)(b*T_SEQ + j)*2048 + h*128 + 64 + (cc-24)*4;
            asm volatile("cp.async.cg.shared.global [%0], [%1], 16;" :: "r"(dst), "l"(src));
        }
    };
    load_k(0, 0);
    asm volatile("cp.async.commit_group;");

    asm volatile("cp.async.wait_group 1;");
    __syncthreads();

    // ---- self score + softmax init ----
    {
        int row = tid >> 2, cg = tid & 3;
        size_t gr = (size_t)(b*T_SEQ + i0 + row);
        const float* ka = klath + gr*2048 + h*128;
        const float* kp = klat  + gr*288 + 256;
        float part = 0.f;
        #pragma unroll
        for (int k = 0; k < 16; k++) {
            int c = 4*k + cg;
            part += Qs[row*QS2 + c] * ka[c];
        }
        #pragma unroll
        for (int k = 0; k < 8; k++) {
            int c = 4*k + cg;
            part += Qs[row*QS2 + 64 + c] * kp[c];
        }
        part += __shfl_xor_sync(0xffffffffu, part, 1, 4);
        part += __shfl_xor_sync(0xffffffffu, part, 2, 4);
        if (cg == 0) { Mrow[row] = part * scale; Lrow[row] = 1.f; }
    }

    // ---- O init = v_abs[self] ----
    float o[4][4];
    {
        size_t r1 = (size_t)(b*T_SEQ + i0 + band*16 + gid);
        const float* v1 = klath + r1*2048 + h*128 + 64;
        const float* v2 = klath + (r1 + 8)*2048 + h*128 + 64;
        #pragma unroll
        for (int nt = 0; nt < 4; nt++) {
            int col = half*32 + nt*8 + tig*2;
            float2 a = *(const float2*)&v1[col];
            float2 c = *(const float2*)&v2[col];
            o[nt][0] = a.x; o[nt][1] = a.y; o[nt][2] = c.x; o[nt][3] = c.y;
        }
    }
    __syncthreads();

    int stage = 0;
    for (int kt0 = 0; 2*kt0 + 1 < i0 + BQ; kt0 += 32) {
        bool more = (2*(kt0+32) + 1 < i0 + BQ);
        if (more) load_k(stage ^ 1, kt0 + 32);
        asm volatile("cp.async.commit_group;");
        asm volatile("cp.async.wait_group 1;");
        __syncthreads();

        const float* ks = Ks + stage*32*KS2;

        // QK^T (raw-bit tf32 feed)
        float sf[2][4];
        #pragma unroll
        for (int nt = 0; nt < 2; nt++)
            #pragma unroll
            for (int i = 0; i < 4; i++) sf[nt][i] = 0.f;
        {
            const float* qb = Qs + (band*16)*QS2;
            const float* kb = ks + (half*16)*KS2;
            #pragma unroll
            for (int kst = 0; kst < 12; kst++) {
                int kc = kst*8 + tig;
                unsigned a0 = __float_as_uint(qb[gid*QS2 + kc]);
                unsigned a1 = __float_as_uint(qb[(gid+8)*QS2 + kc]);
                unsigned a2 = __float_as_uint(qb[gid*QS2 + kc + 4]);
                unsigned a3 = __float_as_uint(qb[(gid+8)*QS2 + kc + 4]);
                #pragma unroll
                for (int nt = 0; nt < 2; nt++) {
                    unsigned b0 = __float_as_uint(kb[(nt*8+gid)*KS2 + kc]);
                    unsigned b1 = __float_as_uint(kb[(nt*8+gid)*KS2 + kc + 4]);
                    asm volatile(
                        "mma.sync.aligned.m16n8k8.row.col.f32.tf32.tf32.f32 "
                        "{%0,%1,%2,%3}, {%4,%5,%6,%7}, {%8,%9}, {%0,%1,%2,%3};"
                        : "+f"(sf[nt][0]), "+f"(sf[nt][1]), "+f"(sf[nt][2]), "+f"(sf[nt][3])
                        : "r"(a0), "r"(a1), "r"(a2), "r"(a3), "r"(b0), "r"(b1));
                }
            }
        }
        #pragma unroll
        for (int nt = 0; nt < 2; nt++) {
            int r = band*16 + gid;
            int c = half*16 + nt*8 + tig*2;
            *(float2*)&Ssm[r*SS + c]     = make_float2(sf[nt][0], sf[nt][1]);
            *(float2*)&Ssm[(r+8)*SS + c] = make_float2(sf[nt][2], sf[nt][3]);
        }
        __syncthreads();

        // online softmax (writes P rounded to tf32 so PV can feed raw bits)
        {
            int row = tid >> 2, cg = tid & 3;
            int iq = i0 + row;
            float vals[8];
            float mx = -1e30f;
            #pragma unroll
            for (int jj = 0; jj < 8; jj++) {
                int col = cg*8 + jj;
                int j = 2*(kt0 + col) + 1;
                float s = (j < iq) ? Ssm[row*SS + col]*scale : -1e30f;
                vals[jj] = s;
                mx = fmaxf(mx, s);
            }
            mx = fmaxf(mx, __shfl_xor_sync(0xffffffffu, mx, 1, 4));
            mx = fmaxf(mx, __shfl_xor_sync(0xffffffffu, mx, 2, 4));
            float mprev = Mrow[row];
            float mnew = fmaxf(mprev, mx);
            float corr = __expf(mprev - mnew);
            float sum = 0.f;
            #pragma unroll
            for (int jj = 0; jj < 8; jj++) {
                float e = __expf(vals[jj] - mnew);
                sum += e;
                Ssm[row*SS + cg*8 + jj] = rnd32(e);
            }
            sum += __shfl_xor_sync(0xffffffffu, sum, 1, 4);
            sum += __shfl_xor_sync(0xffffffffu, sum, 2, 4);
            if (cg == 0) {
                Mrow[row] = mnew;
                Lrow[row] = Lrow[row]*corr + sum;
                Crow[row] = corr;
            }
        }
        __syncthreads();

        // scale O, then P @ V
        {
            float c1 = Crow[band*16 + gid];
            float c2v = Crow[band*16 + gid + 8];
            #pragma unroll
            for (int nt = 0; nt < 4; nt++) {
                o[nt][0] *= c1; o[nt][1] *= c1;
                o[nt][2] *= c2v; o[nt][3] *= c2v;
            }
            const float* pb = Ssm + (band*16)*SS;
            #pragma unroll
            for (int kst = 0; kst < 4; kst++) {
                int kc = kst*8 + tig;
                unsigned a0 = __float_as_uint(pb[gid*SS + kc]);
                unsigned a1 = __float_as_uint(pb[(gid+8)*SS + kc]);
                unsigned a2 = __float_as_uint(pb[gid*SS + kc + 4]);
                unsigned a3 = __float_as_uint(pb[(gid+8)*SS + kc + 4]);
                #pragma unroll
                for (int nt = 0; nt < 4; nt++) {
                    int vc = 96 + half*32 + nt*8 + gid;
                    unsigned b0 = __float_as_uint(ks[(kst*8 + tig)*KS2 + vc]);
                    unsigned b1 = __float_as_uint(ks[(kst*8 + tig + 4)*KS2 + vc]);
                    asm volatile(
                        "mma.sync.aligned.m16n8k8.row.col.f32.tf32.tf32.f32 "
                        "{%0,%1,%2,%3}, {%4,%5,%6,%7}, {%8,%9}, {%0,%1,%2,%3};"
                        : "+f"(o[nt][0]), "+f"(o[nt][1]), "+f"(o[nt][2]), "+f"(o[nt][3])
                        : "r"(a0), "r"(a1), "r"(a2), "r"(a3), "r"(b0), "r"(b1));
                }
            }
        }
        __syncthreads();
        stage ^= 1;
    }

    // ---- epilogue: normalize, round for oproj, store ----
    {
        size_t r1 = (size_t)(b*T_SEQ + i0 + band*16 + gid);
        float li1 = 1.f / Lrow[band*16 + gid];
        float li2 = 1.f / Lrow[band*16 + gid + 8];
        float* x1 = x + r1*1024 + h*64;
        float* x2 = x + (r1 + 8)*1024 + h*64;
        #pragma unroll
        for (int nt = 0; nt < 4; nt++) {
            int col = half*32 + nt*8 + tig*2;
            *(float2*)&x1[col] = make_float2(rnd32(o[nt][0]*li1), rnd32(o[nt][1]*li1));
            *(float2*)&x2[col] = make_float2(rnd32(o[nt][2]*li2), rnd32(o[nt][3]*li2));
        }
    }
}

// ---------------- host ----------------
extern "C" void kernel_launch(void* const* d_in, const int* in_sizes, int n_in,
                              void* d_out, int out_size)
{
    (void)in_sizes; (void)n_in; (void)out_size;
    const float* query    = (const float*)d_in[0];
    const float* key      = (const float*)d_in[1];
    const int*   position = (const int*)d_in[3];
    const float* wq       = (const float*)d_in[4];
    const float* wkv_a    = (const float*)d_in[5];
    const float* kv_gamma = (const float*)d_in[6];
    const float* kv_beta  = (const float*)d_in[7];
    const float* wkv_b    = (const float*)d_in[8];
    const float* wo       = (const float*)d_in[9];
    const float* fc_c_w   = (const float*)d_in[10];
    const float* fc_c_b   = (const float*)d_in[11];
    const float* fc_p_w   = (const float*)d_in[12];
    const float* fc_p_b   = (const float*)d_in[13];
    float* out = (float*)d_out;

    float *kvall, *kvnorm, *q, *klat, *klath, *c2, *p2, *xv, *wbT;
    float *queryr, *keyr, *wqr, *wkvar, *wor;
    cudaGetSymbolAddress((void**)&kvall,  g_kvall);
    cudaGetSymbolAddress((void**)&kvnorm, g_kvnorm);
    cudaGetSymbolAddress((void**)&q,      g_q);
    cudaGetSymbolAddress((void**)&klat,   g_klat);
    cudaGetSymbolAddress((void**)&klath,  g_klath);
    cudaGetSymbolAddress((void**)&c2,     g_c2);
    cudaGetSymbolAddress((void**)&p2,     g_p2);
    cudaGetSymbolAddress((void**)&xv,     g_xv);
    cudaGetSymbolAddress((void**)&wbT,    g_wbT);
    cudaGetSymbolAddress((void**)&queryr, g_queryr);
    cudaGetSymbolAddress((void**)&keyr,   g_keyr);
    cudaGetSymbolAddress((void**)&wqr,    g_wqr);
    cudaGetSymbolAddress((void**)&wkvar,  g_wkvar);
    cudaGetSymbolAddress((void**)&wor,    g_wor);

    cudaFuncSetAttribute(flash_mma_kernel, cudaFuncAttributeMaxDynamicSharedMemorySize, FLASH_SMEM);
    cudaFuncSetAttribute(mma_gemm_kernel, cudaFuncAttributeMaxDynamicSharedMemorySize, MMA_SMEM);

    // 0. tf32 pre-rounding of raw inputs + wkv_b transpose
    round_kernel<<<(ROWS*E_DIM/4+255)/256,256>>>((const float4*)query, (float4*)queryr, ROWS*E_DIM/4);
    round_kernel<<<(ROWS*E_DIM/4+255)/256,256>>>((const float4*)key,   (float4*)keyr,   ROWS*E_DIM/4);
    round_kernel<<<(E_DIM*1536/4+255)/256,256>>>((const float4*)wq,    (float4*)wqr,    E_DIM*1536/4);
    round_kernel<<<(E_DIM*288/4+255)/256,256>>>((const float4*)wkv_a, (float4*)wkvar,  E_DIM*288/4);
    round_kernel<<<(1024*E_DIM/4+255)/256,256>>>((const float4*)wo,    (float4*)wor,    1024*E_DIM/4);
    wbt_kernel<<<2048,256>>>(wkv_b, wbT);

    // 1. kv_all = key @ wkv_a           (4096 x 288 x 2048)
    mma_gemm_kernel<<<dim3(3,32,1),256,MMA_SMEM>>>(
        ROWS,288,E_DIM, keyr,E_DIM,0, wkvar,288,0, kvall,288,0, 0);

    // 2. layernorm + k_pe rope
    kv_post_kernel<<<ROWS,256>>>(kvall, kv_gamma, kv_beta, position, kvnorm, klat);

    // 3. q = query @ wq                 (4096 x 1536 x 2048), rounded out
    mma_gemm_kernel<<<dim3(12,32,1),256,MMA_SMEM>>>(
        ROWS,1536,E_DIM, queryr,E_DIM,0, wqr,1536,0, q,1536,0, 1);

    // 4. q_pe rope (in place, rounded)
    q_rope_kernel<<<ROWS,256>>>(q, position);

    // 5. C2
    c2_kernel<<<1024,256>>>(fc_c_w, fc_c_b, c2);

    // 6. P2 = kv_norm @ fc_p_w + b
    sgemm_kernel<64,64,16,4,4><<<dim3(1,64,1),256>>>(
        ROWS,64,256, kvnorm,256, fc_p_w,64, p2,64, fc_p_b);

    // 7. kv_t gated combine -> klat[0:256] (rounded)
    kvt_kernel<<<ROWS,128>>>(c2, p2, kvnorm, klat);

    // 8. klath = kv_t @ wbT             (4096 x 2048 x 256), rounded out
    mma_gemm_kernel<<<dim3(16,32,1),256,MMA_SMEM>>>(
        ROWS,2048,KVR, klat,DLAT,0, wbT,2048,0, klath,2048,0, 1);

    // 9. flash attention (96-dim QK, 64-dim PV per head)
    flash_mma_kernel<<<dim3(T_SEQ/BQ,NHEAD,B_SZ),256,FLASH_SMEM>>>(q, klat, klath, xv);

    // 10. out = xv @ wo                 (4096 x 2048 x 1024)
    mma_gemm_kernel<<<dim3(16,32,1),256,MMA_SMEM>>>(
        ROWS,E_DIM,1024, xv,1024,0, wor,E_DIM,0, out,E_DIM,0, 0);
}

// round 11
// speedup vs baseline: 1.5629x; 1.0723x over previous
#include <cuda_runtime.h>
#include <math.h>

// Problem constants
#define B_SZ 2
#define T_SEQ 2048
#define E_DIM 2048
#define NHEAD 16
#define NOPE 64
#define ROPE 32
#define VD 64
#define KVR 256
#define QKD 96
#define DLAT 288        // KVR + ROPE
#define ROWS 4096       // B*T

// ---------------- scratch (device globals: allocation-free) ----------------
__device__ float g_kvall[ROWS * 288];
__device__ float g_kvnorm[ROWS * 256];
__device__ float g_q[ROWS * 1536];          // tf32-rounded; per head [nope|roped pe]
__device__ float g_klat[ROWS * DLAT];       // tf32-rounded; [0:256]=kv_t, [256:288]=k_pe
__device__ float g_klath[ROWS * 2048];      // tf32-rounded; per (row,h): [kabs|vabs]
__device__ float g_c2[T_SEQ * 64];
__device__ float g_p2[ROWS * 64];
__device__ float g_xv[ROWS * 1024];         // tf32-rounded attention output
__device__ float g_wbT[256 * 2048];         // tf32-rounded transpose of wkv_b
// tf32-rounded copies of raw inputs
__device__ float g_queryr[ROWS * E_DIM];
__device__ float g_keyr[ROWS * E_DIM];
__device__ float g_wqr[E_DIM * 1536];
__device__ float g_wkvar[E_DIM * 288];
__device__ float g_wor[1024 * E_DIM];

__device__ __forceinline__ unsigned f2tf32(float f) {
    unsigned r; asm("cvt.rna.tf32.f32 %0, %1;" : "=r"(r) : "f"(f)); return r;
}
__device__ __forceinline__ float rnd32(float f) {
    return __uint_as_float(f2tf32(f));
}

// ---------------- fused tf32-round copy of all 5 raw inputs ----------------
#define RN1 (ROWS*E_DIM/4)
#define RN2 (2*RN1)
#define RN3 (RN2 + E_DIM*1536/4)
#define RN4 (RN3 + E_DIM*288/4)
#define RN5 (RN4 + 1024*E_DIM/4)

__global__ void round_all_kernel(
    const float4* __restrict__ q,   float4* __restrict__ qd,
    const float4* __restrict__ k,   float4* __restrict__ kd,
    const float4* __restrict__ wq,  float4* __restrict__ wqd,
    const float4* __restrict__ wkva,float4* __restrict__ wkvad,
    const float4* __restrict__ wo,  float4* __restrict__ wod)
{
    int i = blockIdx.x * 256 + threadIdx.x;
    const float4* s; float4* d; int off;
    if (i < RN1)      { s = q;    d = qd;    off = i; }
    else if (i < RN2) { s = k;    d = kd;    off = i - RN1; }
    else if (i < RN3) { s = wq;   d = wqd;   off = i - RN2; }
    else if (i < RN4) { s = wkva; d = wkvad; off = i - RN3; }
    else if (i < RN5) { s = wo;   d = wod;   off = i - RN4; }
    else return;
    float4 v = s[off];
    v.x = rnd32(v.x); v.y = rnd32(v.y); v.z = rnd32(v.z); v.w = rnd32(v.w);
    d[off] = v;
}

// ============================================================================
// TF32 tensor-core GEMM (inputs pre-rounded to tf32; no cvt in mainloop)
// 2 CTAs/SM: smem 71.7KB x2 = 143KB, 128 regs x 512 thr = full RF.
// ============================================================================
#define MMA_BM 128
#define MMA_BN 128
#define MMA_BK 32
#define AS_STRIDE 36
#define BS_STRIDE 136
#define STAGE_A (MMA_BM * AS_STRIDE)
#define STAGE_B (MMA_BK * BS_STRIDE)
#define MMA_SMEM (2 * (STAGE_A + STAGE_B) * 4)

__global__ __launch_bounds__(256, 2) void mma_gemm_kernel(
    int M, int N, int K,
    const float* __restrict__ A, int lda, long long sA,
    const float* __restrict__ B, int ldb, long long sB,
    float* __restrict__ C, int ldc, long long sC,
    int round_out)
{
    extern __shared__ float smf[];
    float* As = smf;
    float* Bs = smf + 2 * STAGE_A;

    A += (long long)blockIdx.z * sA;
    B += (long long)blockIdx.z * sB;
    C += (long long)blockIdx.z * sC;

    const int tid  = threadIdx.x;
    const int lane = tid & 31;
    const int wid  = tid >> 5;
    const int warp_m = (wid & 1) * 64;
    const int warp_n = (wid >> 1) * 32;
    const int bm = blockIdx.y * MMA_BM;
    const int bn = blockIdx.x * MMA_BN;

    float acc[4][4][4];
    #pragma unroll
    for (int mt = 0; mt < 4; mt++)
        #pragma unroll
        for (int nt = 0; nt < 4; nt++)
            #pragma unroll
            for (int i = 0; i < 4; i++) acc[mt][nt][i] = 0.f;

    const int nk = K / MMA_BK;

    auto load_stage = [&](int stage, int k0) {
        #pragma unroll
        for (int i = 0; i < 4; i++) {
            int c = tid + 256 * i;
            int row = c >> 3, col = (c & 7) * 4;
            unsigned dst = (unsigned)__cvta_generic_to_shared(
                &As[stage * STAGE_A + row * AS_STRIDE + col]);
            const float* src = A + (size_t)(bm + row) * lda + k0 + col;
            asm volatile("cp.async.cg.shared.global [%0], [%1], 16;"
                         :: "r"(dst), "l"(src));
        }
        #pragma unroll
        for (int i = 0; i < 4; i++) {
            int c = tid + 256 * i;
            int k = c >> 5, col = (c & 31) * 4;
            unsigned dst = (unsigned)__cvta_generic_to_shared(
                &Bs[stage * STAGE_B + k * BS_STRIDE + col]);
            int gn = bn + col;
            bool ok = (gn < N);
            const float* src = ok ? (B + (size_t)(k0 + k) * ldb + gn) : B;
            int sz = ok ? 16 : 0;
            asm volatile("cp.async.cg.shared.global [%0], [%1], 16, %2;"
                         :: "r"(dst), "l"(src), "r"(sz));
        }
    };

    load_stage(0, 0);
    asm volatile("cp.async.commit_group;");

    for (int kt = 0; kt < nk; kt++) {
        if (kt + 1 < nk) load_stage((kt + 1) & 1, (kt + 1) * MMA_BK);
        asm volatile("cp.async.commit_group;");
        asm volatile("cp.async.wait_group 1;");
        __syncthreads();

        const float* a_s = As + (kt & 1) * STAGE_A;
        const float* b_s = Bs + (kt & 1) * STAGE_B;

        #pragma unroll
        for (int kk = 0; kk < 4; kk++) {
            const int kb = kk * 8;
            unsigned af[4][4], bf[4][2];
            #pragma unroll
            for (int mt = 0; mt < 4; mt++) {
                int r0 = warp_m + mt * 16 + (lane >> 2);
                int kc = kb + (lane & 3);
                af[mt][0] = __float_as_uint(a_s[r0 * AS_STRIDE + kc]);
                af[mt][1] = __float_as_uint(a_s[(r0 + 8) * AS_STRIDE + kc]);
                af[mt][2] = __float_as_uint(a_s[r0 * AS_STRIDE + kc + 4]);
                af[mt][3] = __float_as_uint(a_s[(r0 + 8) * AS_STRIDE + kc + 4]);
            }
            #pragma unroll
            for (int nt = 0; nt < 4; nt++) {
                int col = warp_n + nt * 8 + (lane >> 2);
                bf[nt][0] = __float_as_uint(b_s[(kb + (lane & 3)) * BS_STRIDE + col]);
                bf[nt][1] = __float_as_uint(b_s[(kb + 4 + (lane & 3)) * BS_STRIDE + col]);
            }
            #pragma unroll
            for (int mt = 0; mt < 4; mt++)
                #pragma unroll
                for (int nt = 0; nt < 4; nt++)
                    asm volatile(
                        "mma.sync.aligned.m16n8k8.row.col.f32.tf32.tf32.f32 "
                        "{%0,%1,%2,%3}, {%4,%5,%6,%7}, {%8,%9}, {%0,%1,%2,%3};"
                        : "+f"(acc[mt][nt][0]), "+f"(acc[mt][nt][1]),
                          "+f"(acc[mt][nt][2]), "+f"(acc[mt][nt][3])
                        : "r"(af[mt][0]), "r"(af[mt][1]), "r"(af[mt][2]), "r"(af[mt][3]),
                          "r"(bf[nt][0]), "r"(bf[nt][1]));
        }
        __syncthreads();
    }

    #pragma unroll
    for (int mt = 0; mt < 4; mt++) {
        #pragma unroll
        for (int nt = 0; nt < 4; nt++) {
            int r0 = bm + warp_m + mt * 16 + (lane >> 2);
            int cn = bn + warp_n + nt * 8 + (lane & 3) * 2;
            if (cn < N) {
                float v0 = acc[mt][nt][0], v1 = acc[mt][nt][1];
                float v2 = acc[mt][nt][2], v3 = acc[mt][nt][3];
                if (round_out) {
                    v0 = rnd32(v0); v1 = rnd32(v1); v2 = rnd32(v2); v3 = rnd32(v3);
                }
                *(float2*)&C[(size_t)r0 * ldc + cn]       = make_float2(v0, v1);
                *(float2*)&C[(size_t)(r0 + 8) * ldc + cn] = make_float2(v2, v3);
            }
        }
    }
}

// ---------------- transpose + round wkv_b: wbT[c][n] = wkv_b[n][c] ----------------
__global__ void wbt_kernel(const float* __restrict__ wkv_b, float* __restrict__ wbT)
{
    int idx = blockIdx.x * 256 + threadIdx.x;
    int n = idx & 2047, c = idx >> 11;
    wbT[(size_t)c * 2048 + n] = rnd32(wkv_b[(size_t)n * 256 + c]);
}

// ---------------- small FFMA SGEMM (P2 only) ----------------
template<int BM,int BN,int BK,int TM,int TN>
__global__ void sgemm_kernel(int M,int N,int K,
    const float* __restrict__ A,int lda,
    const float* __restrict__ B,int ldb,
    float* __restrict__ C,int ldc,
    const float* __restrict__ bias)
{
    constexpr int THREADS=(BM/TM)*(BN/TN);
    __shared__ float As[BK][BM+1];
    __shared__ float Bs[BK][BN+1];
    const int bm = blockIdx.y*BM, bn = blockIdx.x*BN;
    const int tid = threadIdx.x;
    const int tcol = tid % (BN/TN), trow = tid / (BN/TN);
    float acc[TM][TN];
    #pragma unroll
    for (int i=0;i<TM;i++)
        #pragma unroll
        for (int j=0;j<TN;j++) acc[i][j]=0.f;

    for (int k0=0;k0<K;k0+=BK) {
        for (int idx=tid; idx<BM*BK; idx+=THREADS) {
            int m = idx / BK, kk = idx - m*BK;
            int gm = bm+m, gk = k0+kk;
            As[kk][m] = (gm<M && gk<K) ? A[(long long)gm*lda+gk] : 0.f;
        }
        for (int idx=tid; idx<BK*BN; idx+=THREADS) {
            int kk = idx / BN, n = idx - kk*BN;
            int gk = k0+kk, gn = bn+n;
            Bs[kk][n] = (gk<K && gn<N) ? B[(long long)gk*ldb+gn] : 0.f;
        }
        __syncthreads();
        #pragma unroll
        for (int kk=0;kk<BK;kk++) {
            float ra[TM], rb[TN];
            #pragma unroll
            for (int i=0;i<TM;i++) ra[i] = As[kk][trow*TM+i];
            #pragma unroll
            for (int j=0;j<TN;j++) rb[j] = Bs[kk][tcol*TN+j];
            #pragma unroll
            for (int i=0;i<TM;i++)
                #pragma unroll
                for (int j=0;j<TN;j++) acc[i][j] += ra[i]*rb[j];
        }
        __syncthreads();
    }
    #pragma unroll
    for (int i=0;i<TM;i++) {
        int gm = bm + trow*TM + i;
        if (gm >= M) continue;
        #pragma unroll
        for (int j=0;j<TN;j++) {
            int gn = bn + tcol*TN + j;
            if (gn < N) {
                float v = acc[i][j];
                if (bias) v += bias[gn];
                C[(long long)gm*ldc+gn] = v;
            }
        }
    }
}

// ---------------- kv post: layernorm(kv) + rope(k_pe), shfl reductions ----------------
__global__ void kv_post_kernel(const float* __restrict__ kvall,
                               const float* __restrict__ gamma,
                               const float* __restrict__ beta,
                               const int* __restrict__ position,
                               float* __restrict__ kvnorm,
                               float* __restrict__ klat)
{
    int row = blockIdx.x;
    int tid = threadIdx.x;
    int lane = tid & 31, wid = tid >> 5;
    __shared__ float wred[8];

    float v = kvall[(size_t)row*288 + tid];

    float s = v;
    #pragma unroll
    for (int o=16;o>0;o>>=1) s += __shfl_xor_sync(0xffffffffu, s, o);
    if (lane == 0) wred[wid] = s;
    __syncthreads();
    float mean = 0.f;
    #pragma unroll
    for (int i=0;i<8;i++) mean += wred[i];
    mean *= (1.f/256.f);
    __syncthreads();

    float d = v - mean;
    float s2 = d*d;
    #pragma unroll
    for (int o=16;o>0;o>>=1) s2 += __shfl_xor_sync(0xffffffffu, s2, o);
    if (lane == 0) wred[wid] = s2;
    __syncthreads();
    float var = 0.f;
    #pragma unroll
    for (int i=0;i<8;i++) var += wred[i];
    var *= (1.f/256.f);

    float rstd = rsqrtf(var + 1e-5f);
    kvnorm[(size_t)row*256 + tid] = d*rstd*gamma[tid] + beta[tid];

    if (tid < 16) {
        int t = row & (T_SEQ-1);
        float pos = (float)position[t];
        float freq = expf(-(float)(2*tid) * (9.2103403719761836f/32.f));
        float a = pos * freq;
        float c = cosf(a), sn = sinf(a);
        float x0 = kvall[(size_t)row*288 + 256 + 2*tid];
        float x1 = kvall[(size_t)row*288 + 257 + 2*tid];
        klat[(size_t)row*288 + 256 + 2*tid] = rnd32(x0*c - x1*sn);
        klat[(size_t)row*288 + 257 + 2*tid] = rnd32(x0*sn + x1*c);
    }
}

// ---------------- rope for q_pe, IN PLACE (rounded) ----------------
__global__ void q_rope_kernel(float* __restrict__ q,
                              const int* __restrict__ position)
{
    int row = blockIdx.x;
    int tid = threadIdx.x;          // 256 = 16 heads * 16 pairs
    int h = tid >> 4, i = tid & 15;
    int t = row & (T_SEQ-1);
    float pos = (float)position[t];
    float freq = expf(-(float)(2*i) * (9.2103403719761836f/32.f));
    float a = pos * freq;
    float c = cosf(a), s = sinf(a);
    float* qr = q + (size_t)row*1536 + h*96 + 64;
    float x0 = qr[2*i], x1 = qr[2*i+1];
    qr[2*i]   = rnd32(x0*c - x1*s);
    qr[2*i+1] = rnd32(x0*s + x1*c);
}

// ---------------- C2 ----------------
__global__ void c2_kernel(const float* __restrict__ w,
                          const float* __restrict__ bias,
                          float* __restrict__ c2)
{
    __shared__ float pe[256];
    int p = blockIdx.x;
    int tid = threadIdx.x;
    int i = tid >> 1;
    float freq = expf(-(float)(2*i) * (9.2103403719761836f/256.f));
    float a = (float)p * freq;
    pe[tid] = (tid & 1) ? cosf(a) : sinf(a);
    __syncthreads();
    if (tid < 64) {
        float acc = bias[tid];
        for (int k=0;k<256;k++) acc += pe[k]*w[k*64+tid];
        c2[(size_t)(2*p)*64 + tid]   = acc;
        c2[(size_t)(2*p+1)*64 + tid] = acc;
    }
}

// ---------------- kv_t gated combine -> klat[...,0:256] (rounded) ----------------
__global__ void kvt_kernel(const float* __restrict__ c2,
                           const float* __restrict__ p2,
                           const float* __restrict__ kvnorm,
                           float* __restrict__ klat)
{
    int row = blockIdx.x;
    int tid = threadIdx.x;
    int t = row & (T_SEQ-1);
    __shared__ float r1[64], r2[64];
    if (tid < 64) {
        float a = c2[(size_t)t*64 + tid];
        r1[tid] = a * p2[(size_t)row*64 + tid];
        r2[tid] = (t & 1) ? a * p2[(size_t)(row-1)*64 + tid] : 0.f;
    }
    __syncthreads();
    for (int s=32;s>0;s>>=1){ if (tid<s){ r1[tid]+=r1[tid+s]; r2[tid]+=r2[tid+s]; } __syncthreads(); }
    float wself = 1.f/(1.f+expf(-r1[0]));
    float wprev = (t & 1) ? 1.f/(1.f+expf(-r2[0])) : 0.f;
    for (int c=tid; c<256; c+=128) {
        float v = wself * kvnorm[(size_t)row*256 + c];
        if (t & 1) v += wprev * kvnorm[(size_t)(row-1)*256 + c];
        klat[(size_t)row*288 + c] = rnd32(v);
    }
}

// ============================================================================
// Tensor-core flash attention (operands pre-rounded tf32; raw-bit feed)
// Q: 96-dim. K packed: [kabs(64)|kpe(32)|vabs(64)] = 160.
// Heavy blocks (large i0) launched FIRST for wave balance.
// ============================================================================
#define BQ 64
#define QS2 100
#define KS2 164
#define SS 36
#define FLASH_SMEM ((BQ*QS2 + 2*32*KS2 + BQ*SS + 3*BQ) * 4)

__global__ __launch_bounds__(256, 2) void flash_mma_kernel(
    const float* __restrict__ q,
    const float* __restrict__ klat,
    const float* __restrict__ klath,
    float* __restrict__ x)
{
    extern __shared__ float sm[];
    float* Qs   = sm;                       // 64 x 100
    float* Ks   = sm + BQ*QS2;              // 2 x 32 x 164
    float* Ssm  = Ks + 2*32*KS2;            // 64 x 36
    float* Mrow = Ssm + BQ*SS;              // 64
    float* Lrow = Mrow + BQ;                // 64
    float* Crow = Lrow + BQ;                // 64

    const int i0 = (gridDim.x - 1 - blockIdx.x) * BQ;   // heavy blocks first
    const int h  = blockIdx.y;
    const int b  = blockIdx.z;
    const int tid  = threadIdx.x;
    const int lane = tid & 31;
    const int wid  = tid >> 5;
    const int band = wid >> 1;
    const int half = wid & 1;
    const int gid  = lane >> 2;
    const int tig  = lane & 3;
    const float scale = 0.10206207261596575f;  // 1/sqrt(96)

    const float* qbase = q + (size_t)(b*T_SEQ + i0)*1536 + h*96;
    #pragma unroll
    for (int i = 0; i < 6; i++) {
        int c = tid + 256*i;
        int r = c / 24, c4 = c % 24;
        unsigned dst = (unsigned)__cvta_generic_to_shared(&Qs[r*QS2 + c4*4]);
        const float* src = qbase + (size_t)r*1536 + c4*4;
        asm volatile("cp.async.cg.shared.global [%0], [%1], 16;" :: "r"(dst), "l"(src));
    }
    asm volatile("cp.async.commit_group;");

    auto load_k = [&](int stage, int kt0) {
        #pragma unroll
        for (int i = 0; i < 5; i++) {
            int c = tid + 256*i;
            int r = c / 40, cc = c % 40;
            int j = 2*(kt0 + r) + 1;
            if (j > T_SEQ-1) j = T_SEQ-1;
            unsigned dst = (unsigned)__cvta_generic_to_shared(
                &Ks[stage*32*KS2 + r*KS2 + cc*4]);
            const float* src;
            if (cc < 16)       src = klath + (size_t)(b*T_SEQ + j)*2048 + h*128 + cc*4;
            else if (cc < 24)  src = klat  + (size_t)(b*T_SEQ + j)*288 + 256 + (cc-16)*4;
            else               src = klath + (size_t)(b*T_SEQ + j)*2048 + h*128 + 64 + (cc-24)*4;
            asm volatile("cp.async.cg.shared.global [%0], [%1], 16;" :: "r"(dst), "l"(src));
        }
    };
    load_k(0, 0);
    asm volatile("cp.async.commit_group;");

    asm volatile("cp.async.wait_group 1;");
    __syncthreads();

    // ---- self score + softmax init ----
    {
        int row = tid >> 2, cg = tid & 3;
        size_t gr = (size_t)(b*T_SEQ + i0 + row);
        const float* ka = klath + gr*2048 + h*128;
        const float* kp = klat  + gr*288 + 256;
        float part = 0.f;
        #pragma unroll
        for (int k = 0; k < 16; k++) {
            int c = 4*k + cg;
            part += Qs[row*QS2 + c] * ka[c];
        }
        #pragma unroll
        for (int k = 0; k < 8; k++) {
            int c = 4*k + cg;
            part += Qs[row*QS2 + 64 + c] * kp[c];
        }
        part += __shfl_xor_sync(0xffffffffu, part, 1, 4);
        part += __shfl_xor_sync(0xffffffffu, part, 2, 4);
        if (cg == 0) { Mrow[row] = part * scale; Lrow[row] = 1.f; }
    }

    // ---- O init = v_abs[self] ----
    float o[4][4];
    {
        size_t r1 = (size_t)(b*T_SEQ + i0 + band*16 + gid);
        const float* v1 = klath + r1*2048 + h*128 + 64;
        const float* v2 = klath + (r1 + 8)*2048 + h*128 + 64;
        #pragma unroll
        for (int nt = 0; nt < 4; nt++) {
            int col = half*32 + nt*8 + tig*2;
            float2 a = *(const float2*)&v1[col];
            float2 c = *(const float2*)&v2[col];
            o[nt][0] = a.x; o[nt][1] = a.y; o[nt][2] = c.x; o[nt][3] = c.y;
        }
    }
    __syncthreads();

    int stage = 0;
    for (int kt0 = 0; 2*kt0 + 1 < i0 + BQ; kt0 += 32) {
        bool more = (2*(kt0+32) + 1 < i0 + BQ);
        if (more) load_k(stage ^ 1, kt0 + 32);
        asm volatile("cp.async.commit_group;");
        asm volatile("cp.async.wait_group 1;");
        __syncthreads();

        const float* ks = Ks + stage*32*KS2;

        // QK^T (raw-bit tf32 feed)
        float sf[2][4];
        #pragma unroll
        for (int nt = 0; nt < 2; nt++)
            #pragma unroll
            for (int i = 0; i < 4; i++) sf[nt][i] = 0.f;
        {
            const float* qb = Qs + (band*16)*QS2;
            const float* kb = ks + (half*16)*KS2;
            #pragma unroll
            for (int kst = 0; kst < 12; kst++) {
                int kc = kst*8 + tig;
                unsigned a0 = __float_as_uint(qb[gid*QS2 + kc]);
                unsigned a1 = __float_as_uint(qb[(gid+8)*QS2 + kc]);
                unsigned a2 = __float_as_uint(qb[gid*QS2 + kc + 4]);
                unsigned a3 = __float_as_uint(qb[(gid+8)*QS2 + kc + 4]);
                #pragma unroll
                for (int nt = 0; nt < 2; nt++) {
                    unsigned b0 = __float_as_uint(kb[(nt*8+gid)*KS2 + kc]);
                    unsigned b1 = __float_as_uint(kb[(nt*8+gid)*KS2 + kc + 4]);
                    asm volatile(
                        "mma.sync.aligned.m16n8k8.row.col.f32.tf32.tf32.f32 "
                        "{%0,%1,%2,%3}, {%4,%5,%6,%7}, {%8,%9}, {%0,%1,%2,%3};"
                        : "+f"(sf[nt][0]), "+f"(sf[nt][1]), "+f"(sf[nt][2]), "+f"(sf[nt][3])
                        : "r"(a0), "r"(a1), "r"(a2), "r"(a3), "r"(b0), "r"(b1));
                }
            }
        }
        #pragma unroll
        for (int nt = 0; nt < 2; nt++) {
            int r = band*16 + gid;
            int c = half*16 + nt*8 + tig*2;
            *(float2*)&Ssm[r*SS + c]     = make_float2(sf[nt][0], sf[nt][1]);
            *(float2*)&Ssm[(r+8)*SS + c] = make_float2(sf[nt][2], sf[nt][3]);
        }
        __syncthreads();

        // online softmax (writes P rounded to tf32 so PV can feed raw bits)
        {
            int row = tid >> 2, cg = tid & 3;
            int iq = i0 + row;
            float vals[8];
            float mx = -1e30f;
            #pragma unroll
            for (int jj = 0; jj < 8; jj++) {
                int col = cg*8 + jj;
                int j = 2*(kt0 + col) + 1;
                float s = (j < iq) ? Ssm[row*SS + col]*scale : -1e30f;
                vals[jj] = s;
                mx = fmaxf(mx, s);
            }
            mx = fmaxf(mx, __shfl_xor_sync(0xffffffffu, mx, 1, 4));
            mx = fmaxf(mx, __shfl_xor_sync(0xffffffffu, mx, 2, 4));
            float mprev = Mrow[row];
            float mnew = fmaxf(mprev, mx);
            float corr = __expf(mprev - mnew);
            float sum = 0.f;
            #pragma unroll
            for (int jj = 0; jj < 8; jj++) {
                float e = __expf(vals[jj] - mnew);
                sum += e;
                Ssm[row*SS + cg*8 + jj] = rnd32(e);
            }
            sum += __shfl_xor_sync(0xffffffffu, sum, 1, 4);
            sum += __shfl_xor_sync(0xffffffffu, sum, 2, 4);
            if (cg == 0) {
                Mrow[row] = mnew;
                Lrow[row] = Lrow[row]*corr + sum;
                Crow[row] = corr;
            }
        }
        __syncthreads();

        // scale O, then P @ V
        {
            float c1 = Crow[band*16 + gid];
            float c2v = Crow[band*16 + gid + 8];
            #pragma unroll
            for (int nt = 0; nt < 4; nt++) {
                o[nt][0] *= c1; o[nt][1] *= c1;
                o[nt][2] *= c2v; o[nt][3] *= c2v;
            }
            const float* pb = Ssm + (band*16)*SS;
            #pragma unroll
            for (int kst = 0; kst < 4; kst++) {
                int kc = kst*8 + tig;
                unsigned a0 = __float_as_uint(pb[gid*SS + kc]);
                unsigned a1 = __float_as_uint(pb[(gid+8)*SS + kc]);
                unsigned a2 = __float_as_uint(pb[gid*SS + kc + 4]);
                unsigned a3 = __float_as_uint(pb[(gid+8)*SS + kc + 4]);
                #pragma unroll
                for (int nt = 0; nt < 4; nt++) {
                    int vc = 96 + half*32 + nt*8 + gid;
                    unsigned b0 = __float_as_uint(ks[(kst*8 + tig)*KS2 + vc]);
                    unsigned b1 = __float_as_uint(ks[(kst*8 + tig + 4)*KS2 + vc]);
                    asm volatile(
                        "mma.sync.aligned.m16n8k8.row.col.f32.tf32.tf32.f32 "
                        "{%0,%1,%2,%3}, {%4,%5,%6,%7}, {%8,%9}, {%0,%1,%2,%3};"
                        : "+f"(o[nt][0]), "+f"(o[nt][1]), "+f"(o[nt][2]), "+f"(o[nt][3])
                        : "r"(a0), "r"(a1), "r"(a2), "r"(a3), "r"(b0), "r"(b1));
                }
            }
        }
        __syncthreads();
        stage ^= 1;
    }

    // ---- epilogue: normalize, round for oproj, store ----
    {
        size_t r1 = (size_t)(b*T_SEQ + i0 + band*16 + gid);
        float li1 = 1.f / Lrow[band*16 + gid];
        float li2 = 1.f / Lrow[band*16 + gid + 8];
        float* x1 = x + r1*1024 + h*64;
        float* x2 = x + (r1 + 8)*1024 + h*64;
        #pragma unroll
        for (int nt = 0; nt < 4; nt++) {
            int col = half*32 + nt*8 + tig*2;
            *(float2*)&x1[col] = make_float2(rnd32(o[nt][0]*li1), rnd32(o[nt][1]*li1));
            *(float2*)&x2[col] = make_float2(rnd32(o[nt][2]*li2), rnd32(o[nt][3]*li2));
        }
    }
}

// ---------------- host ----------------
extern "C" void kernel_launch(void* const* d_in, const int* in_sizes, int n_in,
                              void* d_out, int out_size)
{
    (void)in_sizes; (void)n_in; (void)out_size;
    const float* query    = (const float*)d_in[0];
    const float* key      = (const float*)d_in[1];
    const int*   position = (const int*)d_in[3];
    const float* wq       = (const float*)d_in[4];
    const float* wkv_a    = (const float*)d_in[5];
    const float* kv_gamma = (const float*)d_in[6];
    const float* kv_beta  = (const float*)d_in[7];
    const float* wkv_b    = (const float*)d_in[8];
    const float* wo       = (const float*)d_in[9];
    const float* fc_c_w   = (const float*)d_in[10];
    const float* fc_c_b   = (const float*)d_in[11];
    const float* fc_p_w   = (const float*)d_in[12];
    const float* fc_p_b   = (const float*)d_in[13];
    float* out = (float*)d_out;

    float *kvall, *kvnorm, *q, *klat, *klath, *c2, *p2, *xv, *wbT;
    float *queryr, *keyr, *wqr, *wkvar, *wor;
    cudaGetSymbolAddress((void**)&kvall,  g_kvall);
    cudaGetSymbolAddress((void**)&kvnorm, g_kvnorm);
    cudaGetSymbolAddress((void**)&q,      g_q);
    cudaGetSymbolAddress((void**)&klat,   g_klat);
    cudaGetSymbolAddress((void**)&klath,  g_klath);
    cudaGetSymbolAddress((void**)&c2,     g_c2);
    cudaGetSymbolAddress((void**)&p2,     g_p2);
    cudaGetSymbolAddress((void**)&xv,     g_xv);
    cudaGetSymbolAddress((void**)&wbT,    g_wbT);
    cudaGetSymbolAddress((void**)&queryr, g_queryr);
    cudaGetSymbolAddress((void**)&keyr,   g_keyr);
    cudaGetSymbolAddress((void**)&wqr,    g_wqr);
    cudaGetSymbolAddress((void**)&wkvar,  g_wkvar);
    cudaGetSymbolAddress((void**)&wor,    g_wor);

    cudaFuncSetAttribute(flash_mma_kernel, cudaFuncAttributeMaxDynamicSharedMemorySize, FLASH_SMEM);
    cudaFuncSetAttribute(mma_gemm_kernel, cudaFuncAttributeMaxDynamicSharedMemorySize, MMA_SMEM);

    // 0. fused tf32 pre-rounding of raw inputs + wkv_b transpose
    round_all_kernel<<<(RN5+255)/256,256>>>(
        (const float4*)query, (float4*)queryr,
        (const float4*)key,   (float4*)keyr,
        (const float4*)wq,    (float4*)wqr,
        (const float4*)wkv_a, (float4*)wkvar,
        (const float4*)wo,    (float4*)wor);
    wbt_kernel<<<2048,256>>>(wkv_b, wbT);

    // 1. kv_all = key @ wkv_a           (4096 x 288 x 2048)
    mma_gemm_kernel<<<dim3(3,32,1),256,MMA_SMEM>>>(
        ROWS,288,E_DIM, keyr,E_DIM,0, wkvar,288,0, kvall,288,0, 0);

    // 2. layernorm + k_pe rope
    kv_post_kernel<<<ROWS,256>>>(kvall, kv_gamma, kv_beta, position, kvnorm, klat);

    // 3. q = query @ wq                 (4096 x 1536 x 2048), rounded out
    mma_gemm_kernel<<<dim3(12,32,1),256,MMA_SMEM>>>(
        ROWS,1536,E_DIM, queryr,E_DIM,0, wqr,1536,0, q,1536,0, 1);

    // 4. q_pe rope (in place, rounded)
    q_rope_kernel<<<ROWS,256>>>(q, position);

    // 5. C2
    c2_kernel<<<1024,256>>>(fc_c_w, fc_c_b, c2);

    // 6. P2 = kv_norm @ fc_p_w + b
    sgemm_kernel<64,64,16,4,4><<<dim3(1,64,1),256>>>(
        ROWS,64,256, kvnorm,256, fc_p_w,64, p2,64, fc_p_b);

    // 7. kv_t gated combine -> klat[0:256] (rounded)
    kvt_kernel<<<ROWS,128>>>(c2, p2, kvnorm, klat);

    // 8. klath = kv_t @ wbT             (4096 x 2048 x 256), rounded out
    mma_gemm_kernel<<<dim3(16,32,1),256,MMA_SMEM>>>(
        ROWS,2048,KVR, klat,DLAT,0, wbT,2048,0, klath,2048,0, 1);

    // 9. flash attention (96-dim QK, 64-dim PV per head), heavy blocks first
    flash_mma_kernel<<<dim3(T_SEQ/BQ,NHEAD,B_SZ),256,FLASH_SMEM>>>(q, klat, klath, xv);

    // 10. out = xv @ wo                 (4096 x 2048 x 1024)
    mma_gemm_kernel<<<dim3(16,32,1),256,MMA_SMEM>>>(
        ROWS,E_DIM,1024, xv,1024,0, wor,E_DIM,0, out,E_DIM,0, 0);
}

// round 13
// speedup vs baseline: 1.6083x; 1.0290x over previous
#include <cuda_runtime.h>
#include <math.h>

// Problem constants
#define B_SZ 2
#define T_SEQ 2048
#define E_DIM 2048
#define NHEAD 16
#define NOPE 64
#define ROPE 32
#define VD 64
#define KVR 256
#define QKD 96
#define DLAT 288        // KVR + ROPE
#define ROWS 4096       // B*T

// ---------------- scratch (device globals: allocation-free) ----------------
__device__ float g_kvall[ROWS * 288];
__device__ float g_kvnorm[ROWS * 256];
__device__ float g_q[ROWS * 1536];          // tf32-rounded; per head [nope|roped pe]
__device__ float g_klat[ROWS * DLAT];       // tf32-rounded; [0:256]=kv_t, [256:288]=k_pe
__device__ float g_klath[ROWS * 2048];      // tf32-rounded; per (row,h): [kabs|vabs]
__device__ float g_c2[T_SEQ * 64];
__device__ float g_p2[ROWS * 64];
__device__ float g_xv[ROWS * 1024];         // tf32-rounded attention output
__device__ float g_wbT[256 * 2048];         // tf32-rounded transpose of wkv_b
// tf32-rounded copies of raw inputs
__device__ float g_queryr[ROWS * E_DIM];
__device__ float g_keyr[ROWS * E_DIM];
__device__ float g_wqr[E_DIM * 1536];
__device__ float g_wkvar[E_DIM * 288];
__device__ float g_wor[1024 * E_DIM];

__device__ __forceinline__ unsigned f2tf32(float f) {
    unsigned r; asm("cvt.rna.tf32.f32 %0, %1;" : "=r"(r) : "f"(f)); return r;
}
__device__ __forceinline__ float rnd32(float f) {
    return __uint_as_float(f2tf32(f));
}

// ---------------- tf32-round copies (split per dependency chain) ----------------
// q-chain: query + wq
#define QN1 (ROWS*E_DIM/4)
#define QN2 (QN1 + E_DIM*1536/4)
__global__ void round_q_kernel(
    const float4* __restrict__ q,  float4* __restrict__ qd,
    const float4* __restrict__ wq, float4* __restrict__ wqd)
{
    int i = blockIdx.x * 256 + threadIdx.x;
    const float4* s; float4* d; int off;
    if (i < QN1)      { s = q;  d = qd;  off = i; }
    else if (i < QN2) { s = wq; d = wqd; off = i - QN1; }
    else return;
    float4 v = s[off];
    v.x = rnd32(v.x); v.y = rnd32(v.y); v.z = rnd32(v.z); v.w = rnd32(v.w);
    d[off] = v;
}
// kv-chain: key + wkv_a + wo
#define KN1 (ROWS*E_DIM/4)
#define KN2 (KN1 + E_DIM*288/4)
#define KN3 (KN2 + 1024*E_DIM/4)
__global__ void round_k_kernel(
    const float4* __restrict__ k,    float4* __restrict__ kd,
    const float4* __restrict__ wkva, float4* __restrict__ wkvad,
    const float4* __restrict__ wo,   float4* __restrict__ wod)
{
    int i = blockIdx.x * 256 + threadIdx.x;
    const float4* s; float4* d; int off;
    if (i < KN1)      { s = k;    d = kd;    off = i; }
    else if (i < KN2) { s = wkva; d = wkvad; off = i - KN1; }
    else if (i < KN3) { s = wo;   d = wod;   off = i - KN2; }
    else return;
    float4 v = s[off];
    v.x = rnd32(v.x); v.y = rnd32(v.y); v.z = rnd32(v.z); v.w = rnd32(v.w);
    d[off] = v;
}

// ============================================================================
// TF32 tensor-core GEMM (inputs pre-rounded to tf32; no cvt in mainloop)
// ============================================================================
#define MMA_BM 128
#define MMA_BN 128
#define MMA_BK 32
#define AS_STRIDE 36
#define BS_STRIDE 136
#define STAGE_A (MMA_BM * AS_STRIDE)
#define STAGE_B (MMA_BK * BS_STRIDE)
#define MMA_SMEM (2 * (STAGE_A + STAGE_B) * 4)

__global__ __launch_bounds__(256, 2) void mma_gemm_kernel(
    int M, int N, int K,
    const float* __restrict__ A, int lda, long long sA,
    const float* __restrict__ B, int ldb, long long sB,
    float* __restrict__ C, int ldc, long long sC,
    int round_out)
{
    extern __shared__ float smf[];
    float* As = smf;
    float* Bs = smf + 2 * STAGE_A;

    A += (long long)blockIdx.z * sA;
    B += (long long)blockIdx.z * sB;
    C += (long long)blockIdx.z * sC;

    const int tid  = threadIdx.x;
    const int lane = tid & 31;
    const int wid  = tid >> 5;
    const int warp_m = (wid & 1) * 64;
    const int warp_n = (wid >> 1) * 32;
    const int bm = blockIdx.y * MMA_BM;
    const int bn = blockIdx.x * MMA_BN;

    float acc[4][4][4];
    #pragma unroll
    for (int mt = 0; mt < 4; mt++)
        #pragma unroll
        for (int nt = 0; nt < 4; nt++)
            #pragma unroll
            for (int i = 0; i < 4; i++) acc[mt][nt][i] = 0.f;

    const int nk = K / MMA_BK;

    auto load_stage = [&](int stage, int k0) {
        #pragma unroll
        for (int i = 0; i < 4; i++) {
            int c = tid + 256 * i;
            int row = c >> 3, col = (c & 7) * 4;
            unsigned dst = (unsigned)__cvta_generic_to_shared(
                &As[stage * STAGE_A + row * AS_STRIDE + col]);
            const float* src = A + (size_t)(bm + row) * lda + k0 + col;
            asm volatile("cp.async.cg.shared.global [%0], [%1], 16;"
                         :: "r"(dst), "l"(src));
        }
        #pragma unroll
        for (int i = 0; i < 4; i++) {
            int c = tid + 256 * i;
            int k = c >> 5, col = (c & 31) * 4;
            unsigned dst = (unsigned)__cvta_generic_to_shared(
                &Bs[stage * STAGE_B + k * BS_STRIDE + col]);
            int gn = bn + col;
            bool ok = (gn < N);
            const float* src = ok ? (B + (size_t)(k0 + k) * ldb + gn) : B;
            int sz = ok ? 16 : 0;
            asm volatile("cp.async.cg.shared.global [%0], [%1], 16, %2;"
                         :: "r"(dst), "l"(src), "r"(sz));
        }
    };

    load_stage(0, 0);
    asm volatile("cp.async.commit_group;");

    for (int kt = 0; kt < nk; kt++) {
        if (kt + 1 < nk) load_stage((kt + 1) & 1, (kt + 1) * MMA_BK);
        asm volatile("cp.async.commit_group;");
        asm volatile("cp.async.wait_group 1;");
        __syncthreads();

        const float* a_s = As + (kt & 1) * STAGE_A;
        const float* b_s = Bs + (kt & 1) * STAGE_B;

        #pragma unroll
        for (int kk = 0; kk < 4; kk++) {
            const int kb = kk * 8;
            unsigned af[4][4], bf[4][2];
            #pragma unroll
            for (int mt = 0; mt < 4; mt++) {
                int r0 = warp_m + mt * 16 + (lane >> 2);
                int kc = kb + (lane & 3);
                af[mt][0] = __float_as_uint(a_s[r0 * AS_STRIDE + kc]);
                af[mt][1] = __float_as_uint(a_s[(r0 + 8) * AS_STRIDE + kc]);
                af[mt][2] = __float_as_uint(a_s[r0 * AS_STRIDE + kc + 4]);
                af[mt][3] = __float_as_uint(a_s[(r0 + 8) * AS_STRIDE + kc + 4]);
            }
            #pragma unroll
            for (int nt = 0; nt < 4; nt++) {
                int col = warp_n + nt * 8 + (lane >> 2);
                bf[nt][0] = __float_as_uint(b_s[(kb + (lane & 3)) * BS_STRIDE + col]);
                bf[nt][1] = __float_as_uint(b_s[(kb + 4 + (lane & 3)) * BS_STRIDE + col]);
            }
            #pragma unroll
            for (int mt = 0; mt < 4; mt++)
                #pragma unroll
                for (int nt = 0; nt < 4; nt++)
                    asm volatile(
                        "mma.sync.aligned.m16n8k8.row.col.f32.tf32.tf32.f32 "
                        "{%0,%1,%2,%3}, {%4,%5,%6,%7}, {%8,%9}, {%0,%1,%2,%3};"
                        : "+f"(acc[mt][nt][0]), "+f"(acc[mt][nt][1]),
                          "+f"(acc[mt][nt][2]), "+f"(acc[mt][nt][3])
                        : "r"(af[mt][0]), "r"(af[mt][1]), "r"(af[mt][2]), "r"(af[mt][3]),
                          "r"(bf[nt][0]), "r"(bf[nt][1]));
        }
        __syncthreads();
    }

    #pragma unroll
    for (int mt = 0; mt < 4; mt++) {
        #pragma unroll
        for (int nt = 0; nt < 4; nt++) {
            int r0 = bm + warp_m + mt * 16 + (lane >> 2);
            int cn = bn + warp_n + nt * 8 + (lane & 3) * 2;
            if (cn < N) {
                float v0 = acc[mt][nt][0], v1 = acc[mt][nt][1];
                float v2 = acc[mt][nt][2], v3 = acc[mt][nt][3];
                if (round_out) {
                    v0 = rnd32(v0); v1 = rnd32(v1); v2 = rnd32(v2); v3 = rnd32(v3);
                }
                *(float2*)&C[(size_t)r0 * ldc + cn]       = make_float2(v0, v1);
                *(float2*)&C[(size_t)(r0 + 8) * ldc + cn] = make_float2(v2, v3);
            }
        }
    }
}

// ---------------- transpose + round wkv_b: wbT[c][n] = wkv_b[n][c] ----------------
__global__ void wbt_kernel(const float* __restrict__ wkv_b, float* __restrict__ wbT)
{
    int idx = blockIdx.x * 256 + threadIdx.x;
    int n = idx & 2047, c = idx >> 11;
    wbT[(size_t)c * 2048 + n] = rnd32(wkv_b[(size_t)n * 256 + c]);
}

// ---------------- small FFMA SGEMM (P2 only) ----------------
template<int BM,int BN,int BK,int TM,int TN>
__global__ void sgemm_kernel(int M,int N,int K,
    const float* __restrict__ A,int lda,
    const float* __restrict__ B,int ldb,
    float* __restrict__ C,int ldc,
    const float* __restrict__ bias)
{
    constexpr int THREADS=(BM/TM)*(BN/TN);
    __shared__ float As[BK][BM+1];
    __shared__ float Bs[BK][BN+1];
    const int bm = blockIdx.y*BM, bn = blockIdx.x*BN;
    const int tid = threadIdx.x;
    const int tcol = tid % (BN/TN), trow = tid / (BN/TN);
    float acc[TM][TN];
    #pragma unroll
    for (int i=0;i<TM;i++)
        #pragma unroll
        for (int j=0;j<TN;j++) acc[i][j]=0.f;

    for (int k0=0;k0<K;k0+=BK) {
        for (int idx=tid; idx<BM*BK; idx+=THREADS) {
            int m = idx / BK, kk = idx - m*BK;
            int gm = bm+m, gk = k0+kk;
            As[kk][m] = (gm<M && gk<K) ? A[(long long)gm*lda+gk] : 0.f;
        }
        for (int idx=tid; idx<BK*BN; idx+=THREADS) {
            int kk = idx / BN, n = idx - kk*BN;
            int gk = k0+kk, gn = bn+n;
            Bs[kk][n] = (gk<K && gn<N) ? B[(long long)gk*ldb+gn] : 0.f;
        }
        __syncthreads();
        #pragma unroll
        for (int kk=0;kk<BK;kk++) {
            float ra[TM], rb[TN];
            #pragma unroll
            for (int i=0;i<TM;i++) ra[i] = As[kk][trow*TM+i];
            #pragma unroll
            for (int j=0;j<TN;j++) rb[j] = Bs[kk][tcol*TN+j];
            #pragma unroll
            for (int i=0;i<TM;i++)
                #pragma unroll
                for (int j=0;j<TN;j++) acc[i][j] += ra[i]*rb[j];
        }
        __syncthreads();
    }
    #pragma unroll
    for (int i=0;i<TM;i++) {
        int gm = bm + trow*TM + i;
        if (gm >= M) continue;
        #pragma unroll
        for (int j=0;j<TN;j++) {
            int gn = bn + tcol*TN + j;
            if (gn < N) {
                float v = acc[i][j];
                if (bias) v += bias[gn];
                C[(long long)gm*ldc+gn] = v;
            }
        }
    }
}

// ---------------- kv post: layernorm(kv) + rope(k_pe), shfl reductions ----------------
__global__ void kv_post_kernel(const float* __restrict__ kvall,
                               const float* __restrict__ gamma,
                               const float* __restrict__ beta,
                               const int* __restrict__ position,
                               float* __restrict__ kvnorm,
                               float* __restrict__ klat)
{
    int row = blockIdx.x;
    int tid = threadIdx.x;
    int lane = tid & 31, wid = tid >> 5;
    __shared__ float wred[8];

    float v = kvall[(size_t)row*288 + tid];

    float s = v;
    #pragma unroll
    for (int o=16;o>0;o>>=1) s += __shfl_xor_sync(0xffffffffu, s, o);
    if (lane == 0) wred[wid] = s;
    __syncthreads();
    float mean = 0.f;
    #pragma unroll
    for (int i=0;i<8;i++) mean += wred[i];
    mean *= (1.f/256.f);
    __syncthreads();

    float d = v - mean;
    float s2 = d*d;
    #pragma unroll
    for (int o=16;o>0;o>>=1) s2 += __shfl_xor_sync(0xffffffffu, s2, o);
    if (lane == 0) wred[wid] = s2;
    __syncthreads();
    float var = 0.f;
    #pragma unroll
    for (int i=0;i<8;i++) var += wred[i];
    var *= (1.f/256.f);

    float rstd = rsqrtf(var + 1e-5f);
    kvnorm[(size_t)row*256 + tid] = d*rstd*gamma[tid] + beta[tid];

    if (tid < 16) {
        int t = row & (T_SEQ-1);
        float pos = (float)position[t];
        float freq = expf(-(float)(2*tid) * (9.2103403719761836f/32.f));
        float a = pos * freq;
        float c = cosf(a), sn = sinf(a);
        float x0 = kvall[(size_t)row*288 + 256 + 2*tid];
        float x1 = kvall[(size_t)row*288 + 257 + 2*tid];
        klat[(size_t)row*288 + 256 + 2*tid] = rnd32(x0*c - x1*sn);
        klat[(size_t)row*288 + 257 + 2*tid] = rnd32(x0*sn + x1*c);
    }
}

// ---------------- rope for q_pe, IN PLACE (rounded) ----------------
__global__ void q_rope_kernel(float* __restrict__ q,
                              const int* __restrict__ position)
{
    int row = blockIdx.x;
    int tid = threadIdx.x;          // 256 = 16 heads * 16 pairs
    int h = tid >> 4, i = tid & 15;
    int t = row & (T_SEQ-1);
    float pos = (float)position[t];
    float freq = expf(-(float)(2*i) * (9.2103403719761836f/32.f));
    float a = pos * freq;
    float c = cosf(a), s = sinf(a);
    float* qr = q + (size_t)row*1536 + h*96 + 64;
    float x0 = qr[2*i], x1 = qr[2*i+1];
    qr[2*i]   = rnd32(x0*c - x1*s);
    qr[2*i+1] = rnd32(x0*s + x1*c);
}

// ---------------- C2 ----------------
__global__ void c2_kernel(const float* __restrict__ w,
                          const float* __restrict__ bias,
                          float* __restrict__ c2)
{
    __shared__ float pe[256];
    int p = blockIdx.x;
    int tid = threadIdx.x;
    int i = tid >> 1;
    float freq = expf(-(float)(2*i) * (9.2103403719761836f/256.f));
    float a = (float)p * freq;
    pe[tid] = (tid & 1) ? cosf(a) : sinf(a);
    __syncthreads();
    if (tid < 64) {
        float acc = bias[tid];
        for (int k=0;k<256;k++) acc += pe[k]*w[k*64+tid];
        c2[(size_t)(2*p)*64 + tid]   = acc;
        c2[(size_t)(2*p+1)*64 + tid] = acc;
    }
}

// ---------------- kv_t gated combine -> klat[...,0:256] (rounded) ----------------
__global__ void kvt_kernel(const float* __restrict__ c2,
                           const float* __restrict__ p2,
                           const float* __restrict__ kvnorm,
                           float* __restrict__ klat)
{
    int row = blockIdx.x;
    int tid = threadIdx.x;
    int t = row & (T_SEQ-1);
    __shared__ float r1[64], r2[64];
    if (tid < 64) {
        float a = c2[(size_t)t*64 + tid];
        r1[tid] = a * p2[(size_t)row*64 + tid];
        r2[tid] = (t & 1) ? a * p2[(size_t)(row-1)*64 + tid] : 0.f;
    }
    __syncthreads();
    for (int s=32;s>0;s>>=1){ if (tid<s){ r1[tid]+=r1[tid+s]; r2[tid]+=r2[tid+s]; } __syncthreads(); }
    float wself = 1.f/(1.f+expf(-r1[0]));
    float wprev = (t & 1) ? 1.f/(1.f+expf(-r2[0])) : 0.f;
    for (int c=tid; c<256; c+=128) {
        float v = wself * kvnorm[(size_t)row*256 + c];
        if (t & 1) v += wprev * kvnorm[(size_t)(row-1)*256 + c];
        klat[(size_t)row*288 + c] = rnd32(v);
    }
}

// ============================================================================
// Tensor-core flash attention (operands pre-rounded tf32; raw-bit feed)
// Q: 96-dim. K packed: [kabs(64)|kpe(32)|vabs(64)] = 160.
// Heavy blocks (large i0) launched FIRST for wave balance.
// ============================================================================
#define BQ 64
#define QS2 100
#define KS2 164
#define SS 36
#define FLASH_SMEM ((BQ*QS2 + 2*32*KS2 + BQ*SS + 3*BQ) * 4)

__global__ __launch_bounds__(256, 2) void flash_mma_kernel(
    const float* __restrict__ q,
    const float* __restrict__ klat,
    const float* __restrict__ klath,
    float* __restrict__ x)
{
    extern __shared__ float sm[];
    float* Qs   = sm;                       // 64 x 100
    float* Ks   = sm + BQ*QS2;              // 2 x 32 x 164
    float* Ssm  = Ks + 2*32*KS2;            // 64 x 36
    float* Mrow = Ssm + BQ*SS;              // 64
    float* Lrow = Mrow + BQ;                // 64
    float* Crow = Lrow + BQ;                // 64

    const int i0 = (gridDim.x - 1 - blockIdx.x) * BQ;   // heavy blocks first
    const int h  = blockIdx.y;
    const int b  = blockIdx.z;
    const int tid  = threadIdx.x;
    const int lane = tid & 31;
    const int wid  = tid >> 5;
    const int band = wid >> 1;
    const int half = wid & 1;
    const int gid  = lane >> 2;
    const int tig  = lane & 3;
    const float scale = 0.10206207261596575f;  // 1/sqrt(96)

    const float* qbase = q + (size_t)(b*T_SEQ + i0)*1536 + h*96;
    #pragma unroll
    for (int i = 0; i < 6; i++) {
        int c = tid + 256*i;
        int r = c / 24, c4 = c % 24;
        unsigned dst = (unsigned)__cvta_generic_to_shared(&Qs[r*QS2 + c4*4]);
        const float* src = qbase + (size_t)r*1536 + c4*4;
        asm volatile("cp.async.cg.shared.global [%0], [%1], 16;" :: "r"(dst), "l"(src));
    }
    asm volatile("cp.async.commit_group;");

    auto load_k = [&](int stage, int kt0) {
        #pragma unroll
        for (int i = 0; i < 5; i++) {
            int c = tid + 256*i;
            int r = c / 40, cc = c % 40;
            int j = 2*(kt0 + r) + 1;
            if (j > T_SEQ-1) j = T_SEQ-1;
            unsigned dst = (unsigned)__cvta_generic_to_shared(
                &Ks[stage*32*KS2 + r*KS2 + cc*4]);
            const float* src;
            if (cc < 16)       src = klath + (size_t)(b*T_SEQ + j)*2048 + h*128 + cc*4;
            else if (cc < 24)  src = klat  + (size_t)(b*T_SEQ + j)*288 + 256 + (cc-16)*4;
            else               src = klath + (size_t)(b*T_SEQ + j)*2048 + h*128 + 64 + (cc-24)*4;
            asm volatile("cp.async.cg.shared.global [%0], [%1], 16;" :: "r"(dst), "l"(src));
        }
    };
    load_k(0, 0);
    asm volatile("cp.async.commit_group;");

    asm volatile("cp.async.wait_group 1;");
    __syncthreads();

    // ---- self score + softmax init ----
    {
        int row = tid >> 2, cg = tid & 3;
        size_t gr = (size_t)(b*T_SEQ + i0 + row);
        const float* ka = klath + gr*2048 + h*128;
        const float* kp = klat  + gr*288 + 256;
        float part = 0.f;
        #pragma unroll
        for (int k = 0; k < 16; k++) {
            int c = 4*k + cg;
            part += Qs[row*QS2 + c] * ka[c];
        }
        #pragma unroll
        for (int k = 0; k < 8; k++) {
            int c = 4*k + cg;
            part += Qs[row*QS2 + 64 + c] * kp[c];
        }
        part += __shfl_xor_sync(0xffffffffu, part, 1, 4);
        part += __shfl_xor_sync(0xffffffffu, part, 2, 4);
        if (cg == 0) { Mrow[row] = part * scale; Lrow[row] = 1.f; }
    }

    // ---- O init = v_abs[self] ----
    float o[4][4];
    {
        size_t r1 = (size_t)(b*T_SEQ + i0 + band*16 + gid);
        const float* v1 = klath + r1*2048 + h*128 + 64;
        const float* v2 = klath + (r1 + 8)*2048 + h*128 + 64;
        #pragma unroll
        for (int nt = 0; nt < 4; nt++) {
            int col = half*32 + nt*8 + tig*2;
            float2 a = *(const float2*)&v1[col];
            float2 c = *(const float2*)&v2[col];
            o[nt][0] = a.x; o[nt][1] = a.y; o[nt][2] = c.x; o[nt][3] = c.y;
        }
    }
    __syncthreads();

    int stage = 0;
    for (int kt0 = 0; 2*kt0 + 1 < i0 + BQ; kt0 += 32) {
        bool more = (2*(kt0+32) + 1 < i0 + BQ);
        if (more) load_k(stage ^ 1, kt0 + 32);
        asm volatile("cp.async.commit_group;");
        asm volatile("cp.async.wait_group 1;");
        __syncthreads();

        const float* ks = Ks + stage*32*KS2;

        // QK^T (raw-bit tf32 feed)
        float sf[2][4];
        #pragma unroll
        for (int nt = 0; nt < 2; nt++)
            #pragma unroll
            for (int i = 0; i < 4; i++) sf[nt][i] = 0.f;
        {
            const float* qb = Qs + (band*16)*QS2;
            const float* kb = ks + (half*16)*KS2;
            #pragma unroll
            for (int kst = 0; kst < 12; kst++) {
                int kc = kst*8 + tig;
                unsigned a0 = __float_as_uint(qb[gid*QS2 + kc]);
                unsigned a1 = __float_as_uint(qb[(gid+8)*QS2 + kc]);
                unsigned a2 = __float_as_uint(qb[gid*QS2 + kc + 4]);
                unsigned a3 = __float_as_uint(qb[(gid+8)*QS2 + kc + 4]);
                #pragma unroll
                for (int nt = 0; nt < 2; nt++) {
                    unsigned b0 = __float_as_uint(kb[(nt*8+gid)*KS2 + kc]);
                    unsigned b1 = __float_as_uint(kb[(nt*8+gid)*KS2 + kc + 4]);
                    asm volatile(
                        "mma.sync.aligned.m16n8k8.row.col.f32.tf32.tf32.f32 "
                        "{%0,%1,%2,%3}, {%4,%5,%6,%7}, {%8,%9}, {%0,%1,%2,%3};"
                        : "+f"(sf[nt][0]), "+f"(sf[nt][1]), "+f"(sf[nt][2]), "+f"(sf[nt][3])
                        : "r"(a0), "r"(a1), "r"(a2), "r"(a3), "r"(b0), "r"(b1));
                }
            }
        }
        #pragma unroll
        for (int nt = 0; nt < 2; nt++) {
            int r = band*16 + gid;
            int c = half*16 + nt*8 + tig*2;
            *(float2*)&Ssm[r*SS + c]     = make_float2(sf[nt][0], sf[nt][1]);
            *(float2*)&Ssm[(r+8)*SS + c] = make_float2(sf[nt][2], sf[nt][3]);
        }
        __syncthreads();

        // online softmax (writes P rounded to tf32 so PV can feed raw bits)
        {
            int row = tid >> 2, cg = tid & 3;
            int iq = i0 + row;
            float vals[8];
            float mx = -1e30f;
            #pragma unroll
            for (int jj = 0; jj < 8; jj++) {
                int col = cg*8 + jj;
                int j = 2*(kt0 + col) + 1;
                float s = (j < iq) ? Ssm[row*SS + col]*scale : -1e30f;
                vals[jj] = s;
                mx = fmaxf(mx, s);
            }
            mx = fmaxf(mx, __shfl_xor_sync(0xffffffffu, mx, 1, 4));
            mx = fmaxf(mx, __shfl_xor_sync(0xffffffffu, mx, 2, 4));
            float mprev = Mrow[row];
            float mnew = fmaxf(mprev, mx);
            float corr = __expf(mprev - mnew);
            float sum = 0.f;
            #pragma unroll
            for (int jj = 0; jj < 8; jj++) {
                float e = __expf(vals[jj] - mnew);
                sum += e;
                Ssm[row*SS + cg*8 + jj] = rnd32(e);
            }
            sum += __shfl_xor_sync(0xffffffffu, sum, 1, 4);
            sum += __shfl_xor_sync(0xffffffffu, sum, 2, 4);
            if (cg == 0) {
                Mrow[row] = mnew;
                Lrow[row] = Lrow[row]*corr + sum;
                Crow[row] = corr;
            }
        }
        __syncthreads();

        // scale O, then P @ V
        {
            float c1 = Crow[band*16 + gid];
            float c2v = Crow[band*16 + gid + 8];
            #pragma unroll
            for (int nt = 0; nt < 4; nt++) {
                o[nt][0] *= c1; o[nt][1] *= c1;
                o[nt][2] *= c2v; o[nt][3] *= c2v;
            }
            const float* pb = Ssm + (band*16)*SS;
            #pragma unroll
            for (int kst = 0; kst < 4; kst++) {
                int kc = kst*8 + tig;
                unsigned a0 = __float_as_uint(pb[gid*SS + kc]);
                unsigned a1 = __float_as_uint(pb[(gid+8)*SS + kc]);
                unsigned a2 = __float_as_uint(pb[gid*SS + kc + 4]);
                unsigned a3 = __float_as_uint(pb[(gid+8)*SS + kc + 4]);
                #pragma unroll
                for (int nt = 0; nt < 4; nt++) {
                    int vc = 96 + half*32 + nt*8 + gid;
                    unsigned b0 = __float_as_uint(ks[(kst*8 + tig)*KS2 + vc]);
                    unsigned b1 = __float_as_uint(ks[(kst*8 + tig + 4)*KS2 + vc]);
                    asm volatile(
                        "mma.sync.aligned.m16n8k8.row.col.f32.tf32.tf32.f32 "
                        "{%0,%1,%2,%3}, {%4,%5,%6,%7}, {%8,%9}, {%0,%1,%2,%3};"
                        : "+f"(o[nt][0]), "+f"(o[nt][1]), "+f"(o[nt][2]), "+f"(o[nt][3])
                        : "r"(a0), "r"(a1), "r"(a2), "r"(a3), "r"(b0), "r"(b1));
                }
            }
        }
        __syncthreads();
        stage ^= 1;
    }

    // ---- epilogue: normalize, round for oproj, store ----
    {
        size_t r1 = (size_t)(b*T_SEQ + i0 + band*16 + gid);
        float li1 = 1.f / Lrow[band*16 + gid];
        float li2 = 1.f / Lrow[band*16 + gid + 8];
        float* x1 = x + r1*1024 + h*64;
        float* x2 = x + (r1 + 8)*1024 + h*64;
        #pragma unroll
        for (int nt = 0; nt < 4; nt++) {
            int col = half*32 + nt*8 + tig*2;
            *(float2*)&x1[col] = make_float2(rnd32(o[nt][0]*li1), rnd32(o[nt][1]*li1));
            *(float2*)&x2[col] = make_float2(rnd32(o[nt][2]*li2), rnd32(o[nt][3]*li2));
        }
    }
}

// ---------------- host ----------------
extern "C" void kernel_launch(void* const* d_in, const int* in_sizes, int n_in,
                              void* d_out, int out_size)
{
    (void)in_sizes; (void)n_in; (void)out_size;
    const float* query    = (const float*)d_in[0];
    const float* key      = (const float*)d_in[1];
    const int*   position = (const int*)d_in[3];
    const float* wq       = (const float*)d_in[4];
    const float* wkv_a    = (const float*)d_in[5];
    const float* kv_gamma = (const float*)d_in[6];
    const float* kv_beta  = (const float*)d_in[7];
    const float* wkv_b    = (const float*)d_in[8];
    const float* wo       = (const float*)d_in[9];
    const float* fc_c_w   = (const float*)d_in[10];
    const float* fc_c_b   = (const float*)d_in[11];
    const float* fc_p_w   = (const float*)d_in[12];
    const float* fc_p_b   = (const float*)d_in[13];
    float* out = (float*)d_out;

    float *kvall, *kvnorm, *q, *klat, *klath, *c2, *p2, *xv, *wbT;
    float *queryr, *keyr, *wqr, *wkvar, *wor;
    cudaGetSymbolAddress((void**)&kvall,  g_kvall);
    cudaGetSymbolAddress((void**)&kvnorm, g_kvnorm);
    cudaGetSymbolAddress((void**)&q,      g_q);
    cudaGetSymbolAddress((void**)&klat,   g_klat);
    cudaGetSymbolAddress((void**)&klath,  g_klath);
    cudaGetSymbolAddress((void**)&c2,     g_c2);
    cudaGetSymbolAddress((void**)&p2,     g_p2);
    cudaGetSymbolAddress((void**)&xv,     g_xv);
    cudaGetSymbolAddress((void**)&wbT,    g_wbT);
    cudaGetSymbolAddress((void**)&queryr, g_queryr);
    cudaGetSymbolAddress((void**)&keyr,   g_keyr);
    cudaGetSymbolAddress((void**)&wqr,    g_wqr);
    cudaGetSymbolAddress((void**)&wkvar,  g_wkvar);
    cudaGetSymbolAddress((void**)&wor,    g_wor);

    cudaFuncSetAttribute(flash_mma_kernel, cudaFuncAttributeMaxDynamicSharedMemorySize, FLASH_SMEM);
    cudaFuncSetAttribute(mma_gemm_kernel, cudaFuncAttributeMaxDynamicSharedMemorySize, MMA_SMEM);

    // ---- fork a side stream for the independent q-chain ----
    cudaStream_t s1;
    cudaStreamCreateWithFlags(&s1, cudaStreamNonBlocking);
    cudaEvent_t eFork, eQ;
    cudaEventCreateWithFlags(&eFork, cudaEventDisableTiming);
    cudaEventCreateWithFlags(&eQ,    cudaEventDisableTiming);

    cudaEventRecord(eFork, 0);
    cudaStreamWaitEvent(s1, eFork, 0);

    // ===== q-chain on s1 =====
    round_q_kernel<<<(QN2+255)/256,256,0,s1>>>(
        (const float4*)query, (float4*)queryr,
        (const float4*)wq,    (float4*)wqr);
    mma_gemm_kernel<<<dim3(12,32,1),256,MMA_SMEM,s1>>>(
        ROWS,1536,E_DIM, queryr,E_DIM,0, wqr,1536,0, q,1536,0, 1);
    q_rope_kernel<<<ROWS,256,0,s1>>>(q, position);
    cudaEventRecord(eQ, s1);

    // ===== kv-chain on default stream =====
    round_k_kernel<<<(KN3+255)/256,256>>>(
        (const float4*)key,   (float4*)keyr,
        (const float4*)wkv_a, (float4*)wkvar,
        (const float4*)wo,    (float4*)wor);
    wbt_kernel<<<2048,256>>>(wkv_b, wbT);
    c2_kernel<<<1024,256>>>(fc_c_w, fc_c_b, c2);

    mma_gemm_kernel<<<dim3(3,32,1),256,MMA_SMEM>>>(
        ROWS,288,E_DIM, keyr,E_DIM,0, wkvar,288,0, kvall,288,0, 0);
    kv_post_kernel<<<ROWS,256>>>(kvall, kv_gamma, kv_beta, position, kvnorm, klat);
    sgemm_kernel<64,64,16,4,4><<<dim3(1,64,1),256>>>(
        ROWS,64,256, kvnorm,256, fc_p_w,64, p2,64, fc_p_b);
    kvt_kernel<<<ROWS,128>>>(c2, p2, kvnorm, klat);
    mma_gemm_kernel<<<dim3(16,32,1),256,MMA_SMEM>>>(
        ROWS,2048,KVR, klat,DLAT,0, wbT,2048,0, klath,2048,0, 1);

    // ===== join, then attention + output projection =====
    cudaStreamWaitEvent(0, eQ, 0);
    flash_mma_kernel<<<dim3(T_SEQ/BQ,NHEAD,B_SZ),256,FLASH_SMEM>>>(q, klat, klath, xv);
    mma_gemm_kernel<<<dim3(16,32,1),256,MMA_SMEM>>>(
        ROWS,E_DIM,1024, xv,1024,0, wor,E_DIM,0, out,E_DIM,0, 0);

    cudaStreamDestroy(s1);
    cudaEventDestroy(eFork);
    cudaEventDestroy(eQ);
}